// round 8
// baseline (speedup 1.0000x reference)
#include <cuda_runtime.h>
#include <math.h>

// ---------------- problem constants ----------------
#define D    768
#define DH   3072
#define BB   8
#define TT   8
#define NT   197            // tokens per frame (cls + 196)
#define BT   64             // B*T
#define NHD  12             // heads
#define HD   64             // head dim
#define ST   1569           // T*H*W + 1
#define MXT  (BT*NT)        // 12608 rows in frame-token space
#define MY   (BB*ST)        // 12552 rows in original token space
#define YSZ  (MY*D)         // 9,639,936
#define LMSZ (BT*NT*NT)     // 2,483,776

#define GS   4                        // cp.async pipeline stages
#define ASTG (128*20*4)               // 10240 B per A stage
#define BSTG (64*20*4)                // 5120 B per B stage
#define SMEM_G (GS*(ASTG+BSTG))       // 61440 B -> 3 CTAs/SM

// ---------------- scratch (device globals: allocation-free) ----------------
__device__ float g_xt [MXT*D];
__device__ float g_qmk[MXT*2*D];      // [qm | km] fused
__device__ float g_wqk[2*D*D];        // [Wmq ; Wmk] (tf32-rounded)
__device__ float g_bqk[2*D];
__device__ float g_xn [MXT*D];        // LN1 out, later LN2 out (tf32-rounded)
__device__ float g_qkv[MXT*3*D];
__device__ float g_o  [MXT*D];
__device__ float g_op [MXT*D];
__device__ float g_h  [MY*DH];
__device__ float g_wqkv[3*D*D];       // tf32-rounded weight copies
__device__ float g_wpr [D*D];
__device__ float g_wf1 [DH*D];
__device__ float g_wf2 [D*DH];

// ---------------- helpers ----------------
__device__ __forceinline__ float tf32r(float x) {
    unsigned r;
    asm("cvt.rna.tf32.f32 %0, %1;" : "=r"(r) : "f"(x));
    return __uint_as_float(r);
}

__device__ __forceinline__ void mma8(float* c, const unsigned* a, const unsigned* b) {
    asm volatile(
        "mma.sync.aligned.m16n8k8.row.col.f32.tf32.tf32.f32 "
        "{%0,%1,%2,%3}, {%4,%5,%6,%7}, {%8,%9}, {%0,%1,%2,%3};"
        : "+f"(c[0]), "+f"(c[1]), "+f"(c[2]), "+f"(c[3])
        : "r"(a[0]), "r"(a[1]), "r"(a[2]), "r"(a[3]), "r"(b[0]), "r"(b[1]));
}

__device__ __forceinline__ void ldsm_x4(unsigned* r, unsigned addr) {
    asm volatile("ldmatrix.sync.aligned.m8n8.x4.shared.b16 {%0,%1,%2,%3}, [%4];"
        : "=r"(r[0]), "=r"(r[1]), "=r"(r[2]), "=r"(r[3]) : "r"(addr));
}

__device__ __forceinline__ void cpa16(unsigned dst, const float* src, bool p) {
    asm volatile("cp.async.cg.shared.global [%0], [%1], 16, %2;"
        :: "r"(dst), "l"(src), "r"(p ? 16 : 0));
}
#define CP_COMMIT asm volatile("cp.async.commit_group;")
template<int N> __device__ __forceinline__ void cp_wait() {
    asm volatile("cp.async.wait_group %0;" :: "n"(N));
}

// ---------------- merged weight rounding (writes device globals directly) ----------------
__global__ void round_weights(const float* __restrict__ Wqkv, const float* __restrict__ Wpr,
                              const float* __restrict__ Wf1, const float* __restrict__ Wf2,
                              const float* __restrict__ Wmq, const float* __restrict__ Wmk,
                              const float* __restrict__ bmq, const float* __restrict__ bmk) {
    const int DD = D * D;
    int i = blockIdx.x * blockDim.x + threadIdx.x;
    if (i < 3 * DD)        g_wqkv[i]          = tf32r(Wqkv[i]);
    else if (i < 4 * DD)   g_wpr[i - 3 * DD]  = tf32r(Wpr[i - 3 * DD]);
    else if (i < 8 * DD)   g_wf1[i - 4 * DD]  = tf32r(Wf1[i - 4 * DD]);
    else if (i < 12 * DD)  g_wf2[i - 8 * DD]  = tf32r(Wf2[i - 8 * DD]);
    else if (i < 13 * DD)  g_wqk[i - 12 * DD] = tf32r(Wmq[i - 12 * DD]);
    else if (i < 14 * DD)  g_wqk[DD + i - 13 * DD] = tf32r(Wmk[i - 13 * DD]);
    if (i < D) g_bqk[i] = bmq[i];
    else if (i < 2 * D) g_bqk[i] = bmk[i - D];
}

// ---------------- fused gather + LayerNorm1: x -> xt(tf32), xn(tf32) ----------------
__global__ void gather_ln(const float* __restrict__ x, const float* __restrict__ g,
                          const float* __restrict__ be,
                          float* __restrict__ xt, float* __restrict__ xn) {
    int row = blockIdx.x;
    int tid = threadIdx.x;
    int n  = row % NT;
    int bt = row / NT;
    int b = bt / TT, t = bt % TT;
    int src = (n == 0) ? (b * ST) : (b * ST + 1 + (n - 1) * TT + t);
    const float* xr = x + (long)src * D;
    float v0 = xr[tid], v1 = xr[tid + 256], v2 = xr[tid + 512];
    float* xtr = xt + (long)row * D;
    xtr[tid] = tf32r(v0); xtr[tid + 256] = tf32r(v1); xtr[tid + 512] = tf32r(v2);

    __shared__ float red[256];
    red[tid] = v0 + v1 + v2;
    __syncthreads();
    for (int o = 128; o > 0; o >>= 1) { if (tid < o) red[tid] += red[tid + o]; __syncthreads(); }
    float mean = red[0] * (1.0f / D);
    __syncthreads();
    float d0 = v0 - mean, d1 = v1 - mean, d2 = v2 - mean;
    red[tid] = d0*d0 + d1*d1 + d2*d2;
    __syncthreads();
    for (int o = 128; o > 0; o >>= 1) { if (tid < o) red[tid] += red[tid + o]; __syncthreads(); }
    float rs = rsqrtf(red[0] * (1.0f / D) + 1e-5f);
    float* yr = xn + (long)row * D;
    yr[tid]       = tf32r(d0 * rs * g[tid]       + be[tid]);
    yr[tid + 256] = tf32r(d1 * rs * g[tid + 256] + be[tid + 256]);
    yr[tid + 512] = tf32r(d2 * rs * g[tid + 512] + be[tid + 512]);
}

// ---------------- universal tf32 GEMM: 128x64 tile, 8 warps of 32x32, 3 CTAs/SM ----------------
// Inputs must already be tf32-rounded. C = epi(alpha*A*B^T [+ bias]).
// ep low 3 bits: 0=+bias  1=+bias,gelu  2=+bias,+Res  3=sigmoid w/ forced [0,0]=100
// ep bit 3 (8): round output to tf32
__global__ __launch_bounds__(256, 3) void gemm_tf32(
    const float* __restrict__ A, const float* __restrict__ B,
    const float* __restrict__ bias, const float* __restrict__ Res,
    float* __restrict__ C, int M, int N, int K,
    int lda, int ldb, int ldc,
    int inner, int sAi, int sBi, long long sAo, long long sBo, long long sC,
    float alpha, int ep)
{
    extern __shared__ __align__(16) float dyn[];   // GS A-stages then GS B-stages

    int tid  = threadIdx.x;
    int warp = tid >> 5, lane = tid & 31;
    int g = lane >> 2, tig = lane & 3;
    int wm = warp & 3;      // 0..3 : 32 rows each
    int wn = warp >> 2;     // 0..1 : 32 cols each
    int m0 = blockIdx.y * 128, n0 = blockIdx.x * 64;

    const float* Ab = A;
    const float* Bb = B;
    float* Cb = C;
    if (sC) {
        int z = blockIdx.z;
        int zo = z / inner, zi = z % inner;
        Ab += (long long)zo * sAo + (long long)zi * sAi;
        Bb += (long long)zo * sBo + (long long)zi * sBi;
        Cb += (long long)z * sC;
    }

    // A loader: 256 thr -> 128 rows x 16 cols (two cpa16/thread)
    int lraw = tid >> 1;           // 0..127
    int lcaw = (tid & 1) * 8;      // 0 or 8
    bool aok = (m0 + lraw) < M;
    const float* Ap = Ab + (long long)(m0 + lraw) * lda + lcaw;
    // B loader: 256 thr -> 64 rows x 16 cols (one cpa16/thread)
    int lrbw = tid >> 2;           // 0..63
    int lcbw = (tid & 3) * 4;      // 0,4,8,12
    bool bok = (n0 + lrbw) < N;
    const float* Bp = Bb + (long long)(n0 + lrbw) * ldb + lcbw;

    unsigned smB = (unsigned)__cvta_generic_to_shared(dyn);
    unsigned aSt = smB + (lraw * 20 + lcaw) * 4;
    unsigned bSt = smB + GS * ASTG + (lrbw * 20 + lcbw) * 4;

    // ldmatrix per-thread addresses
    int arow = lane & 15;
    int acol = (lane >> 4) * 4;
    int brow = (lane & 7) + ((lane & 16) >> 1);
    int bcol = ((lane >> 3) & 1) * 4;
    unsigned aAddr = smB + ((wm * 32 + arow) * 20 + acol) * 4;
    unsigned bAddr = smB + GS * ASTG + ((wn * 32 + brow) * 20 + bcol) * 4;

    float acc[2][4][4];
    #pragma unroll
    for (int mt = 0; mt < 2; mt++)
        #pragma unroll
        for (int nt = 0; nt < 4; nt++)
            #pragma unroll
            for (int i = 0; i < 4; i++) acc[mt][nt][i] = 0.f;

    int nkt = K >> 4;

    // prologue: prefetch GS-1 tiles
    #pragma unroll
    for (int s = 0; s < GS - 1; s++) {
        bool has = s < nkt;
        cpa16(aSt + s * ASTG,      Ap + s * 16,     aok && has);
        cpa16(aSt + s * ASTG + 16, Ap + s * 16 + 4, aok && has);
        cpa16(bSt + s * BSTG,      Bp + s * 16,     bok && has);
        CP_COMMIT;
    }

#define LOADFRAG(aB, bB, kko) do { \
        ldsm_x4(fa[0], (aB) + 0 * 1280 + (kko)); \
        ldsm_x4(fa[1], (aB) + 1 * 1280 + (kko)); \
        ldsm_x4(fb2[0], (bB) + 0 * 1280 + (kko)); \
        ldsm_x4(fb2[1], (bB) + 1 * 1280 + (kko)); \
    } while (0)
#define MMA_ALL do { \
        _Pragma("unroll") \
        for (int mt = 0; mt < 2; mt++) \
            _Pragma("unroll") \
            for (int nt = 0; nt < 4; nt++) { \
                unsigned bb[2] = { fb2[nt >> 1][(nt & 1) * 2], fb2[nt >> 1][(nt & 1) * 2 + 1] }; \
                mma8(acc[mt][nt], fa[mt], bb); \
            } \
    } while (0)

    for (int kt = 0; kt < nkt; kt++) {
        cp_wait<GS - 2>();
        __syncthreads();
        int cur = kt & (GS - 1);
        unsigned aB = aAddr + cur * ASTG;
        unsigned bB = bAddr + cur * BSTG;

        {                               // prefetch tile kt+GS-1
            int pf = kt + GS - 1;
            bool has = pf < nkt;
            int ps = pf & (GS - 1);
            cpa16(aSt + ps * ASTG,      Ap + pf * 16,     aok && has);
            cpa16(aSt + ps * ASTG + 16, Ap + pf * 16 + 4, aok && has);
            cpa16(bSt + ps * BSTG,      Bp + pf * 16,     bok && has);
            CP_COMMIT;
        }

        unsigned fa[2][4], fb2[2][4];
        LOADFRAG(aB, bB, 0);
        MMA_ALL;
        LOADFRAG(aB, bB, 32);
        MMA_ALL;
    }
#undef LOADFRAG
#undef MMA_ALL

    int base_ep = ep & 7;
    bool rnd = (ep & 8) != 0;
    bool v2ok = (ldc & 1) == 0;

    // epilogue
    #pragma unroll
    for (int mt = 0; mt < 2; mt++) {
        int r0 = m0 + wm * 32 + mt * 16 + g;
        #pragma unroll
        for (int nt = 0; nt < 4; nt++) {
            int c0 = n0 + wn * 32 + nt * 8 + tig * 2;
            #pragma unroll
            for (int i = 0; i < 2; i++) {
                int rr = r0 + i * 8;
                if (rr >= M) continue;
                float v[2];
                #pragma unroll
                for (int j = 0; j < 2; j++) {
                    int cc = c0 + j;
                    float t = acc[mt][nt][i * 2 + j] * alpha;
                    if (base_ep == 3) {
                        if (rr == 0 && cc == 0) t = 100.0f;
                        t = 1.0f / (1.0f + expf(-t));
                    } else {
                        if (bias) t += bias[cc];
                        if (base_ep == 1) t = 0.5f * t * (1.0f + erff(t * 0.7071067811865476f));
                        else if (base_ep == 2) t += Res[(long long)rr * ldc + cc];
                    }
                    if (rnd) t = tf32r(t);
                    v[j] = t;
                }
                if (v2ok && c0 + 1 < N) {
                    *(float2*)&Cb[(long long)rr * ldc + c0] = make_float2(v[0], v[1]);
                } else {
                    if (c0 < N)     Cb[(long long)rr * ldc + c0] = v[0];
                    if (c0 + 1 < N) Cb[(long long)rr * ldc + c0 + 1] = v[1];
                }
            }
        }
    }
}

// ---------------- fused attention: QK^T (tf32) -> softmax*gate -> AV (tf32) ----------------
// qkv is pre-rounded to tf32.
#define SK 68
#define SP 204
#define SM_Q  0
#define SM_K  (SM_Q + 64*SK)
#define SM_P  (SM_K + 200*SK)
#define SM_V  (SM_P + 64*SP)
#define SM_TOT ((SM_V + 64*SP)*4)

__global__ __launch_bounds__(256, 1) void fused_attn(
    const float* __restrict__ qkv, const float* __restrict__ lm, float* __restrict__ o)
{
    extern __shared__ float sm[];
    float* Qs = sm + SM_Q;
    float* Ks = sm + SM_K;
    float* Ps = sm + SM_P;
    float* Vt = sm + SM_V;

    int tid = threadIdx.x;
    int w = tid >> 5, lane = tid & 31;
    int g = lane >> 2, tig = lane & 3;
    int qi = blockIdx.x, h = blockIdx.y, bt = blockIdx.z;
    int q0 = qi * 64;
    const float* base = qkv + (long)bt * NT * 3 * D + h * HD;

    {
        int r = tid >> 2;
        int c = (tid & 3) * 16;
        int q = q0 + r;
        if (q < NT) {
            const float* p = base + (long)q * 3 * D + c;
            #pragma unroll
            for (int j = 0; j < 4; j++)
                *(float4*)&Qs[r*SK + c + j*4] = *(const float4*)(p + j * 4);
        } else {
            #pragma unroll
            for (int j = 0; j < 16; j++) Qs[r*SK + c + j] = 0.f;
        }
    }
    {
        int c = (tid & 3) * 16;
        for (int r = tid >> 2; r < NT; r += 64) {
            const float* p = base + (long)r * 3 * D + D + c;
            #pragma unroll
            for (int j = 0; j < 4; j++)
                *(float4*)&Ks[r*SK + c + j*4] = *(const float4*)(p + j * 4);
        }
        for (int i = tid; i < 3 * 64; i += 256)
            Ks[(197 + i / 64) * SK + (i % 64)] = 0.f;
    }
    {
        int c4 = (tid & 15) * 4;
        for (int m = tid >> 4; m < NT; m += 16) {
            float4 v = *(const float4*)(base + (long)m * 3 * D + 2 * D + c4);
            Vt[(c4 + 0) * SP + m] = v.x;
            Vt[(c4 + 1) * SP + m] = v.y;
            Vt[(c4 + 2) * SP + m] = v.z;
            Vt[(c4 + 3) * SP + m] = v.w;
        }
        for (int i = tid; i < 64 * 7; i += 256)
            Vt[(i / 7) * SP + 197 + (i % 7)] = 0.f;
    }
    __syncthreads();

    {
        int wm = w & 3;
        int wn = w >> 2;
        int nt0 = wn ? 13 : 0, nt1 = wn ? 25 : 13;
        for (int nt = nt0; nt < nt1; nt++) {
            float c[4] = {0.f, 0.f, 0.f, 0.f};
            #pragma unroll
            for (int kk = 0; kk < 64; kk += 8) {
                unsigned a[4], b[2];
                int ra = wm * 16 + g;
                a[0] = __float_as_uint(Qs[ra*SK + kk + tig]);
                a[1] = __float_as_uint(Qs[(ra + 8)*SK + kk + tig]);
                a[2] = __float_as_uint(Qs[ra*SK + kk + tig + 4]);
                a[3] = __float_as_uint(Qs[(ra + 8)*SK + kk + tig + 4]);
                int rb = nt * 8 + g;
                b[0] = __float_as_uint(Ks[rb*SK + kk + tig]);
                b[1] = __float_as_uint(Ks[rb*SK + kk + tig + 4]);
                mma8(c, a, b);
            }
            int rm = wm * 16 + g, cn = nt * 8 + tig * 2;
            Ps[rm*SP + cn] = c[0];       Ps[rm*SP + cn + 1] = c[1];
            Ps[(rm+8)*SP + cn] = c[2];   Ps[(rm+8)*SP + cn + 1] = c[3];
        }
    }
    __syncthreads();

    {
        for (int rr = 0; rr < 8; rr++) {
            int r = (w << 3) + rr;
            int q = q0 + r;
            if (q < NT) {
                const float* lmr = lm + ((long)bt * NT + q) * NT;
                float mx = -1e30f;
                for (int k = lane; k < NT; k += 32) mx = fmaxf(mx, Ps[r*SP + k]);
                #pragma unroll
                for (int s = 16; s > 0; s >>= 1) mx = fmaxf(mx, __shfl_xor_sync(0xffffffffu, mx, s));
                float sum = 0.f;
                for (int k = lane; k < NT; k += 32) {
                    float e = expf(0.125f * (Ps[r*SP + k] - mx));
                    Ps[r*SP + k] = e;
                    sum += e;
                }
                #pragma unroll
                for (int s = 16; s > 0; s >>= 1) sum += __shfl_xor_sync(0xffffffffu, sum, s);
                float inv = 1.0f / sum;
                for (int k = lane; k < 204; k += 32) {
                    float p = (k < NT) ? tf32r(Ps[r*SP + k] * inv * lmr[k]) : 0.f;
                    Ps[r*SP + k] = p;
                }
            } else {
                for (int k = lane; k < 204; k += 32) Ps[r*SP + k] = 0.f;
            }
        }
    }
    __syncthreads();

    {
        int wmA = w >> 1;
        int wnA = w & 1;
        float acc[4][4];
        #pragma unroll
        for (int nt = 0; nt < 4; nt++)
            #pragma unroll
            for (int i = 0; i < 4; i++) acc[nt][i] = 0.f;

        for (int kk = 0; kk < 200; kk += 8) {
            unsigned a[4], b[4][2];
            int ra = wmA * 16 + g;
            a[0] = __float_as_uint(Ps[ra*SP + kk + tig]);
            a[1] = __float_as_uint(Ps[(ra + 8)*SP + kk + tig]);
            a[2] = __float_as_uint(Ps[ra*SP + kk + tig + 4]);
            a[3] = __float_as_uint(Ps[(ra + 8)*SP + kk + tig + 4]);
            #pragma unroll
            for (int nt = 0; nt < 4; nt++) {
                int rb = wnA * 32 + nt * 8 + g;
                b[nt][0] = __float_as_uint(Vt[rb*SP + kk + tig]);
                b[nt][1] = __float_as_uint(Vt[rb*SP + kk + tig + 4]);
            }
            #pragma unroll
            for (int nt = 0; nt < 4; nt++) mma8(acc[nt], a, b[nt]);
        }

        #pragma unroll
        for (int nt = 0; nt < 4; nt++) {
            int cn = wnA * 32 + nt * 8 + tig * 2;
            #pragma unroll
            for (int i = 0; i < 2; i++) {
                int q = q0 + wmA * 16 + g + i * 8;
                if (q >= NT) continue;
                float* op = o + ((long)bt * NT + q) * D + h * HD + cn;
                op[0] = tf32r(acc[nt][i * 2]);       // o feeds proj GEMM
                op[1] = tf32r(acc[nt][i * 2 + 1]);
            }
        }
    }
}

// ---------------- fused scatter(+residual) + LayerNorm2: y, xn(tf32) ----------------
__global__ void scatter_ln(const float* __restrict__ x, const float* __restrict__ op,
                           const float* __restrict__ g, const float* __restrict__ be,
                           float* __restrict__ y, float* __restrict__ xn) {
    int row = blockIdx.x;
    int tid = threadIdx.x;
    int p = row % ST;
    int b = row / ST;
    float v[3];
    #pragma unroll
    for (int c = 0; c < 3; c++) {
        int d = tid + c * 256;
        float add;
        if (p == 0) {
            float s = 0.f;
            #pragma unroll
            for (int t = 0; t < TT; t++)
                s += op[((long)((b * TT + t) * NT)) * D + d];
            add = s * (1.0f / TT);
        } else {
            int q = p - 1;
            int hw = q / TT, t = q % TT;
            add = op[((long)((b * TT + t) * NT + 1 + hw)) * D + d];
        }
        v[c] = x[(long)row * D + d] + add;
        y[(long)row * D + d] = v[c];
    }
    __shared__ float red[256];
    red[tid] = v[0] + v[1] + v[2];
    __syncthreads();
    for (int o = 128; o > 0; o >>= 1) { if (tid < o) red[tid] += red[tid + o]; __syncthreads(); }
    float mean = red[0] * (1.0f / D);
    __syncthreads();
    float d0 = v[0] - mean, d1 = v[1] - mean, d2 = v[2] - mean;
    red[tid] = d0*d0 + d1*d1 + d2*d2;
    __syncthreads();
    for (int o = 128; o > 0; o >>= 1) { if (tid < o) red[tid] += red[tid + o]; __syncthreads(); }
    float rs = rsqrtf(red[0] * (1.0f / D) + 1e-5f);
    float* yr = xn + (long)row * D;
    yr[tid]       = tf32r(d0 * rs * g[tid]       + be[tid]);
    yr[tid + 256] = tf32r(d1 * rs * g[tid + 256] + be[tid + 256]);
    yr[tid + 512] = tf32r(d2 * rs * g[tid + 512] + be[tid + 512]);
}

// ---------------- launcher ----------------
extern "C" void kernel_launch(void* const* d_in, const int* in_sizes, int n_in,
                              void* d_out, int out_size) {
    const float* x    = (const float*)d_in[0];
    const float* Wmq  = (const float*)d_in[1];
    const float* bmq  = (const float*)d_in[2];
    const float* Wmk  = (const float*)d_in[3];
    const float* bmk  = (const float*)d_in[4];
    const float* g1   = (const float*)d_in[5];
    const float* be1  = (const float*)d_in[6];
    const float* Wqkv = (const float*)d_in[7];
    const float* Wpr  = (const float*)d_in[8];
    const float* bpr  = (const float*)d_in[9];
    const float* g2   = (const float*)d_in[10];
    const float* be2  = (const float*)d_in[11];
    const float* Wf1  = (const float*)d_in[12];
    const float* bf1  = (const float*)d_in[13];
    const float* Wf2  = (const float*)d_in[14];
    const float* bf2  = (const float*)d_in[15];

    float* out = (float*)d_out;
    float* y   = out;
    float* lm  = out + YSZ;

    float *xt, *qmk, *wqk, *bqk, *xn, *qkv, *o, *op, *h;
    float *wqkv, *wpr, *wf1, *wf2;
    cudaGetSymbolAddress((void**)&xt,  g_xt);
    cudaGetSymbolAddress((void**)&qmk, g_qmk);
    cudaGetSymbolAddress((void**)&wqk, g_wqk);
    cudaGetSymbolAddress((void**)&bqk, g_bqk);
    cudaGetSymbolAddress((void**)&xn,  g_xn);
    cudaGetSymbolAddress((void**)&qkv, g_qkv);
    cudaGetSymbolAddress((void**)&o,   g_o);
    cudaGetSymbolAddress((void**)&op,  g_op);
    cudaGetSymbolAddress((void**)&h,   g_h);
    cudaGetSymbolAddress((void**)&wqkv,g_wqkv);
    cudaGetSymbolAddress((void**)&wpr, g_wpr);
    cudaGetSymbolAddress((void**)&wf1, g_wf1);
    cudaGetSymbolAddress((void**)&wf2, g_wf2);

    static int smem_set = 0;
    if (!smem_set) {
        cudaFuncSetAttribute(fused_attn, cudaFuncAttributeMaxDynamicSharedMemorySize, SM_TOT);
        cudaFuncSetAttribute(gemm_tf32, cudaFuncAttributeMaxDynamicSharedMemorySize, SMEM_G);
        smem_set = 1;
    }

    int gy  = (MXT + 127) / 128;   // 99
    int gy2 = (MY  + 127) / 128;   // 99

    // 0) one merged weight-rounding pass
    round_weights<<<(14 * D * D + 255) / 256, 256>>>(Wqkv, Wpr, Wf1, Wf2, Wmq, Wmk, bmq, bmk);

    // 1) gather + LN1 (tf32-rounded outputs)
    gather_ln<<<MXT, 256>>>(x, g1, be1, xt, xn);

    // 2) fused mask projections [qm|km] (round output: feeds lm GEMM)
    gemm_tf32<<<dim3((2*D)/64, gy), 256, SMEM_G>>>(xt, wqk, bqk, nullptr, qmk, MXT, 2*D, D,
                                                   D, D, 2*D, 1,0,0,0,0,0, 1.0f, 0 | 8);

    // 3) lm logits (batched over bt) with fused sigmoid + forced [0,0]=100
    gemm_tf32<<<dim3(4, 2, BT), 256, SMEM_G>>>(qmk, qmk + D, nullptr, nullptr, lm, NT, NT, D,
                                               2*D, 2*D, NT,
                                               1, 0, 0, (long long)NT*2*D, (long long)NT*2*D,
                                               (long long)NT*NT, 1.0f, 3);

    // 4) QKV projection (round output: feeds attention MMAs)
    gemm_tf32<<<dim3((3*D)/64, gy), 256, SMEM_G>>>(xn, wqkv, nullptr, nullptr, qkv, MXT, 3*D, D,
                                                   D, D, 3*D, 1,0,0,0,0,0, 1.0f, 0 | 8);

    // 5) fused attention (QK^T + softmax*gate + AV), rounds o
    fused_attn<<<dim3(4, NHD, BT), 256, SM_TOT>>>(qkv, lm, o);

    // 6) output projection, scatter back (+residual) + LN2
    gemm_tf32<<<dim3(D/64, gy), 256, SMEM_G>>>(o, wpr, bpr, nullptr, op, MXT, D, D,
                                               D, D, D, 1,0,0,0,0,0, 1.0f, 0);
    scatter_ln<<<MY, 256>>>(x, op, g2, be2, y, xn);

    // 7) MLP: fc1(+gelu, round: feeds fc2) -> fc2(+residual into y)
    gemm_tf32<<<dim3(DH/64, gy2), 256, SMEM_G>>>(xn, wf1, bf1, nullptr, h, MY, DH, D,
                                                 D, D, DH, 1,0,0,0,0,0, 1.0f, 1 | 8);
    gemm_tf32<<<dim3(D/64, gy2), 256, SMEM_G>>>(h, wf2, bf2, y, y, MY, D, DH,
                                                DH, DH, D, 1,0,0,0,0,0, 1.0f, 2);
}

// round 13
// speedup vs baseline: 1.5442x; 1.5442x over previous
#include <cuda_runtime.h>
#include <cuda_fp16.h>
#include <math.h>

// ---------------- problem constants ----------------
#define D    768
#define DH   3072
#define BB   8
#define TT   8
#define NT   197
#define BT   64
#define NHD  12
#define HD   64
#define ST   1569
#define MXT  (BT*NT)        // 12608
#define MY   (BB*ST)        // 12552
#define YSZ  (MY*D)
#define LMSZ (BT*NT*NT)

#define GS   4
#define SMEM_G (GS*2*128*20*4)   // 81920 (tf32 stages)
#define SMEM_H (GS*2*128*40*2)   // 81920 (fp16 stages)

// ---------------- scratch ----------------
__device__ __half g_xth [MXT*D];
__device__ __half g_xnh [MXT*D];
__device__ float  g_qmk [MXT*2*D];
__device__ float  g_bqk [2*D];
__device__ float  g_qkv [MXT*3*D];
__device__ __half g_oh  [MXT*D];
__device__ float  g_op  [MXT*D];
__device__ __half g_xn2h[MY*D];
__device__ __half g_hh  [MY*DH];
__device__ __half g_wqkh [2*D*D];
__device__ __half g_wqkvh[3*D*D];
__device__ __half g_wprh [D*D];
__device__ __half g_wf1h [DH*D];
__device__ __half g_wf2h [D*DH];

// ---------------- helpers ----------------
__device__ __forceinline__ float tf32r(float x) {
    unsigned r;
    asm("cvt.rna.tf32.f32 %0, %1;" : "=r"(r) : "f"(x));
    return __uint_as_float(r);
}

__device__ __forceinline__ void mma8(float* c, const unsigned* a, const unsigned* b) {
    asm volatile(
        "mma.sync.aligned.m16n8k8.row.col.f32.tf32.tf32.f32 "
        "{%0,%1,%2,%3}, {%4,%5,%6,%7}, {%8,%9}, {%0,%1,%2,%3};"
        : "+f"(c[0]), "+f"(c[1]), "+f"(c[2]), "+f"(c[3])
        : "r"(a[0]), "r"(a[1]), "r"(a[2]), "r"(a[3]), "r"(b[0]), "r"(b[1]));
}

__device__ __forceinline__ void mma16h(float* c, const unsigned* a, const unsigned* b) {
    asm volatile(
        "mma.sync.aligned.m16n8k16.row.col.f32.f16.f16.f32 "
        "{%0,%1,%2,%3}, {%4,%5,%6,%7}, {%8,%9}, {%0,%1,%2,%3};"
        : "+f"(c[0]), "+f"(c[1]), "+f"(c[2]), "+f"(c[3])
        : "r"(a[0]), "r"(a[1]), "r"(a[2]), "r"(a[3]), "r"(b[0]), "r"(b[1]));
}

__device__ __forceinline__ void ldsm_x4(unsigned* r, unsigned addr) {
    asm volatile("ldmatrix.sync.aligned.m8n8.x4.shared.b16 {%0,%1,%2,%3}, [%4];"
        : "=r"(r[0]), "=r"(r[1]), "=r"(r[2]), "=r"(r[3]) : "r"(addr));
}

__device__ __forceinline__ void cpa16(unsigned dst, const void* src, bool p) {
    asm volatile("cp.async.cg.shared.global [%0], [%1], 16, %2;"
        :: "r"(dst), "l"(src), "r"(p ? 16 : 0));
}
#define CP_COMMIT asm volatile("cp.async.commit_group;")
template<int N> __device__ __forceinline__ void cp_wait() {
    asm volatile("cp.async.wait_group %0;" :: "n"(N));
}

// ---------------- merged weight prep (all fp16) ----------------
__global__ void round_weights(const float* __restrict__ Wqkv, const float* __restrict__ Wpr,
                              const float* __restrict__ Wf1, const float* __restrict__ Wf2,
                              const float* __restrict__ Wmq, const float* __restrict__ Wmk,
                              const float* __restrict__ bmq, const float* __restrict__ bmk) {
    const int DD = D * D;
    int i = blockIdx.x * blockDim.x + threadIdx.x;
    if (i < 3 * DD)        g_wqkvh[i]          = __float2half(Wqkv[i]);
    else if (i < 4 * DD)   g_wprh[i - 3 * DD]  = __float2half(Wpr[i - 3 * DD]);
    else if (i < 8 * DD)   g_wf1h[i - 4 * DD]  = __float2half(Wf1[i - 4 * DD]);
    else if (i < 12 * DD)  g_wf2h[i - 8 * DD]  = __float2half(Wf2[i - 8 * DD]);
    else if (i < 13 * DD)  g_wqkh[i - 12 * DD] = __float2half(Wmq[i - 12 * DD]);
    else if (i < 14 * DD)  g_wqkh[DD + i - 13 * DD] = __float2half(Wmk[i - 13 * DD]);
    if (i < D) g_bqk[i] = bmq[i];
    else if (i < 2 * D) g_bqk[i] = bmk[i - D];
}

// ---------------- fused gather + LayerNorm1 -> xth, xnh (fp16) ----------------
__global__ void gather_ln(const float* __restrict__ x, const float* __restrict__ g,
                          const float* __restrict__ be,
                          __half* __restrict__ xth, __half* __restrict__ xnh) {
    int row = blockIdx.x;
    int tid = threadIdx.x;
    int n  = row % NT;
    int bt = row / NT;
    int b = bt / TT, t = bt % TT;
    int src = (n == 0) ? (b * ST) : (b * ST + 1 + (n - 1) * TT + t);
    const float* xr = x + (long)src * D;
    float v0 = xr[tid], v1 = xr[tid + 256], v2 = xr[tid + 512];
    __half* xtr = xth + (long)row * D;
    xtr[tid] = __float2half(v0); xtr[tid + 256] = __float2half(v1); xtr[tid + 512] = __float2half(v2);

    __shared__ float red[256];
    red[tid] = v0 + v1 + v2;
    __syncthreads();
    for (int o = 128; o > 0; o >>= 1) { if (tid < o) red[tid] += red[tid + o]; __syncthreads(); }
    float mean = red[0] * (1.0f / D);
    __syncthreads();
    float d0 = v0 - mean, d1 = v1 - mean, d2 = v2 - mean;
    red[tid] = d0*d0 + d1*d1 + d2*d2;
    __syncthreads();
    for (int o = 128; o > 0; o >>= 1) { if (tid < o) red[tid] += red[tid + o]; __syncthreads(); }
    float rs = rsqrtf(red[0] * (1.0f / D) + 1e-5f);
    __half* yr = xnh + (long)row * D;
    yr[tid]       = __float2half(d0 * rs * g[tid]       + be[tid]);
    yr[tid + 256] = __float2half(d1 * rs * g[tid + 256] + be[tid + 256]);
    yr[tid + 512] = __float2half(d2 * rs * g[tid + 512] + be[tid + 512]);
}

// ---------------- tf32 GEMM (R6 loop shape) — lm logits only ----------------
// ep low 3 bits: 0=+bias 1=gelu 2=+Res 3=sigmoid w/ forced [0,0]=100 ; bit3: round tf32
__global__ __launch_bounds__(256, 2) void gemm_tf32(
    const float* __restrict__ A, const float* __restrict__ B,
    const float* __restrict__ bias, const float* __restrict__ Res,
    float* __restrict__ C, int M, int N, int K,
    int lda, int ldb, int ldc,
    int inner, int sAi, int sBi, long long sAo, long long sBo, long long sC,
    float alpha, int ep)
{
    extern __shared__ __align__(16) float dyn[];

    int tid  = threadIdx.x;
    int warp = tid >> 5, lane = tid & 31;
    int g = lane >> 2, tig = lane & 3;
    int wm = warp >> 2;
    int wn = warp & 3;
    int m0 = blockIdx.y * 128, n0 = blockIdx.x * 128;

    const float* Ab = A;
    const float* Bb = B;
    float* Cb = C;
    if (sC) {
        int z = blockIdx.z;
        int zo = z / inner, zi = z % inner;
        Ab += (long long)zo * sAo + (long long)zi * sAi;
        Bb += (long long)zo * sBo + (long long)zi * sBi;
        Cb += (long long)z * sC;
    }

    int ldrow = tid >> 1;
    int ldcol = (tid & 1) * 8;
    bool aok = (m0 + ldrow) < M;
    bool bok = (n0 + ldrow) < N;
    const float* Ap = Ab + (long long)(m0 + ldrow) * lda + ldcol;
    const float* Bp = Bb + (long long)(n0 + ldrow) * ldb + ldcol;

    unsigned smB = (unsigned)__cvta_generic_to_shared(dyn);
    const unsigned STG = 128 * 20 * 4;
    unsigned aSt = smB + (ldrow * 20 + ldcol) * 4;
    unsigned bSt = smB + GS * STG + (ldrow * 20 + ldcol) * 4;

    int arow = lane & 15;
    int acol = (lane >> 4) * 4;
    int brow = (lane & 7) + ((lane & 16) >> 1);
    int bcol = ((lane >> 3) & 1) * 4;
    unsigned aAddr = smB + ((wm * 64 + arow) * 20 + acol) * 4;
    unsigned bAddr = smB + GS * STG + ((wn * 32 + brow) * 20 + bcol) * 4;

    float acc[4][4][4];
    #pragma unroll
    for (int mt = 0; mt < 4; mt++)
        #pragma unroll
        for (int nt = 0; nt < 4; nt++)
            #pragma unroll
            for (int i = 0; i < 4; i++) acc[mt][nt][i] = 0.f;

    int nkt = K >> 4;

    #pragma unroll
    for (int s = 0; s < GS - 1; s++) {
        bool has = s < nkt;
        cpa16(aSt + s * STG,      Ap + s * 16,     aok && has);
        cpa16(aSt + s * STG + 16, Ap + s * 16 + 4, aok && has);
        cpa16(bSt + s * STG,      Bp + s * 16,     bok && has);
        cpa16(bSt + s * STG + 16, Bp + s * 16 + 4, bok && has);
        CP_COMMIT;
    }

#define LOADFRAG(aB, bB, kko) do { \
        ldsm_x4(fa[0], (aB) + 0 * 1280 + (kko)); \
        ldsm_x4(fa[1], (aB) + 1 * 1280 + (kko)); \
        ldsm_x4(fa[2], (aB) + 2 * 1280 + (kko)); \
        ldsm_x4(fa[3], (aB) + 3 * 1280 + (kko)); \
        ldsm_x4(fb2[0], (bB) + 0 * 1280 + (kko)); \
        ldsm_x4(fb2[1], (bB) + 1 * 1280 + (kko)); \
    } while (0)
#define MMA_ALL do { \
        _Pragma("unroll") \
        for (int mt = 0; mt < 4; mt++) \
            _Pragma("unroll") \
            for (int nt = 0; nt < 4; nt++) { \
                unsigned bb[2] = { fb2[nt >> 1][(nt & 1) * 2], fb2[nt >> 1][(nt & 1) * 2 + 1] }; \
                mma8(acc[mt][nt], fa[mt], bb); \
            } \
    } while (0)

    for (int kt = 0; kt < nkt; kt++) {
        cp_wait<GS - 2>();
        __syncthreads();
        int cur = kt & (GS - 1);
        unsigned aB = aAddr + cur * STG;
        unsigned bB = bAddr + cur * STG;

        {
            int pf = kt + GS - 1;
            bool has = pf < nkt;
            int ps = pf & (GS - 1);
            cpa16(aSt + ps * STG,      Ap + pf * 16,     aok && has);
            cpa16(aSt + ps * STG + 16, Ap + pf * 16 + 4, aok && has);
            cpa16(bSt + ps * STG,      Bp + pf * 16,     bok && has);
            cpa16(bSt + ps * STG + 16, Bp + pf * 16 + 4, bok && has);
            CP_COMMIT;
        }

        unsigned fa[4][4], fb2[2][4];
        LOADFRAG(aB, bB, 0);
        MMA_ALL;
        LOADFRAG(aB, bB, 32);
        MMA_ALL;
    }
#undef LOADFRAG
#undef MMA_ALL

    int base_ep = ep & 7;
    bool rnd = (ep & 8) != 0;
    bool v2ok = (ldc & 1) == 0;

    #pragma unroll
    for (int mt = 0; mt < 4; mt++) {
        int r0 = m0 + wm * 64 + mt * 16 + g;
        #pragma unroll
        for (int nt = 0; nt < 4; nt++) {
            int c0 = n0 + wn * 32 + nt * 8 + tig * 2;
            #pragma unroll
            for (int i = 0; i < 2; i++) {
                int rr = r0 + i * 8;
                if (rr >= M) continue;
                float v[2];
                #pragma unroll
                for (int j = 0; j < 2; j++) {
                    int cc = c0 + j;
                    float t = acc[mt][nt][i * 2 + j] * alpha;
                    if (base_ep == 3) {
                        if (rr == 0 && cc == 0) t = 100.0f;
                        t = 1.0f / (1.0f + expf(-t));
                    } else {
                        if (bias) t += bias[cc];
                        if (base_ep == 1) t = 0.5f * t * (1.0f + erff(t * 0.7071067811865476f));
                        else if (base_ep == 2) t += Res[(long long)rr * ldc + cc];
                    }
                    if (rnd) t = tf32r(t);
                    v[j] = t;
                }
                if (v2ok && c0 + 1 < N) {
                    *(float2*)&Cb[(long long)rr * ldc + c0] = make_float2(v[0], v[1]);
                } else {
                    if (c0 < N)     Cb[(long long)rr * ldc + c0] = v[0];
                    if (c0 + 1 < N) Cb[(long long)rr * ldc + c0 + 1] = v[1];
                }
            }
        }
    }
}

// ---------------- fp16 GEMM: m16n8k16, K-tile=32 halves (64 B/row) ----------------
// A: MxK f16 (lda), B: NxK f16 (ldb). C = epi(A*B^T [+bias]).
// ep low 3 bits: 0=+bias 1=+bias,gelu 2=+bias,+Res ; bit3 (8): round out tf32 ; bit4 (16): out fp16 to Ch
__global__ __launch_bounds__(256, 2) void gemm_h16(
    const __half* __restrict__ A, const __half* __restrict__ B,
    const float* __restrict__ bias, const float* __restrict__ Res,
    float* __restrict__ C, __half* __restrict__ Ch,
    int M, int N, int K, int lda, int ldb, int ldc, int ep)
{
    extern __shared__ __align__(16) float dyn[];

    int tid  = threadIdx.x;
    int warp = tid >> 5, lane = tid & 31;
    int g = lane >> 2, tig = lane & 3;
    int wm = warp >> 2;
    int wn = warp & 3;
    int m0 = blockIdx.y * 128, n0 = blockIdx.x * 128;

    // loaders: 128 rows x 64B; 2 threads/row, each owns chunks lch,lch+1 (16B each)
    int lrow = tid >> 1;
    int lch  = (tid & 1) * 2;
    bool aok = (m0 + lrow) < M;
    bool bok = (n0 + lrow) < N;
    const __half* Ap = A + (long long)(m0 + lrow) * lda + lch * 8;
    const __half* Bp = B + (long long)(n0 + lrow) * ldb + lch * 8;

    unsigned smB = (unsigned)__cvta_generic_to_shared(dyn);
    const unsigned STG = 128 * 40 * 2;     // 10240 B (row stride 80 B)
    unsigned aSt = smB + lrow * 80 + lch * 16;
    unsigned bSt = smB + GS * STG + lrow * 80 + lch * 16;

    int arow = lane & 15;
    int acolB = (lane >> 4) * 16;
    int brow = (lane & 7) + ((lane & 16) >> 1);
    int bcolB = ((lane >> 3) & 1) * 16;
    unsigned aAddr = smB + (wm * 64 + arow) * 80 + acolB;
    unsigned bAddr = smB + GS * STG + (wn * 32 + brow) * 80 + bcolB;

    float acc[4][4][4];
    #pragma unroll
    for (int mt = 0; mt < 4; mt++)
        #pragma unroll
        for (int nt = 0; nt < 4; nt++)
            #pragma unroll
            for (int i = 0; i < 4; i++) acc[mt][nt][i] = 0.f;

    int nkt = K >> 5;

    #pragma unroll
    for (int s = 0; s < GS - 1; s++) {
        bool has = s < nkt;
        cpa16(aSt + s * STG,      Ap + s * 32,     aok && has);
        cpa16(aSt + s * STG + 16, Ap + s * 32 + 8, aok && has);
        cpa16(bSt + s * STG,      Bp + s * 32,     bok && has);
        cpa16(bSt + s * STG + 16, Bp + s * 32 + 8, bok && has);
        CP_COMMIT;
    }

#define LOADFRAGH(aB, bB, kko) do { \
        ldsm_x4(fa[0], (aB) + 0 * 1280 + (kko)); \
        ldsm_x4(fa[1], (aB) + 1 * 1280 + (kko)); \
        ldsm_x4(fa[2], (aB) + 2 * 1280 + (kko)); \
        ldsm_x4(fa[3], (aB) + 3 * 1280 + (kko)); \
        ldsm_x4(fb2[0], (bB) + 0 * 1280 + (kko)); \
        ldsm_x4(fb2[1], (bB) + 1 * 1280 + (kko)); \
    } while (0)
#define MMAH_ALL do { \
        _Pragma("unroll") \
        for (int mt = 0; mt < 4; mt++) \
            _Pragma("unroll") \
            for (int nt = 0; nt < 4; nt++) { \
                unsigned bb[2] = { fb2[nt >> 1][(nt & 1) * 2], fb2[nt >> 1][(nt & 1) * 2 + 1] }; \
                mma16h(acc[mt][nt], fa[mt], bb); \
            } \
    } while (0)

    for (int kt = 0; kt < nkt; kt++) {
        cp_wait<GS - 2>();
        __syncthreads();
        int cur = kt & (GS - 1);
        unsigned aB = aAddr + cur * STG;
        unsigned bB = bAddr + cur * STG;

        {
            int pf = kt + GS - 1;
            bool has = pf < nkt;
            int ps = pf & (GS - 1);
            cpa16(aSt + ps * STG,      Ap + pf * 32,     aok && has);
            cpa16(aSt + ps * STG + 16, Ap + pf * 32 + 8, aok && has);
            cpa16(bSt + ps * STG,      Bp + pf * 32,     bok && has);
            cpa16(bSt + ps * STG + 16, Bp + pf * 32 + 8, bok && has);
            CP_COMMIT;
        }

        unsigned fa[4][4], fb2[2][4];
        LOADFRAGH(aB, bB, 0);     // k 0..15
        MMAH_ALL;
        LOADFRAGH(aB, bB, 32);    // k 16..31
        MMAH_ALL;
    }
#undef LOADFRAGH
#undef MMAH_ALL

    int base_ep = ep & 7;
    bool rnd = (ep & 8) != 0;
    bool outh = (ep & 16) != 0;

    #pragma unroll
    for (int mt = 0; mt < 4; mt++) {
        int r0 = m0 + wm * 64 + mt * 16 + g;
        #pragma unroll
        for (int nt = 0; nt < 4; nt++) {
            int c0 = n0 + wn * 32 + nt * 8 + tig * 2;
            #pragma unroll
            for (int i = 0; i < 2; i++) {
                int rr = r0 + i * 8;
                if (rr >= M) continue;
                float v[2];
                #pragma unroll
                for (int j = 0; j < 2; j++) {
                    int cc = c0 + j;
                    float t = acc[mt][nt][i * 2 + j];
                    if (bias) t += bias[cc];
                    if (base_ep == 1) t = 0.5f * t * (1.0f + erff(t * 0.7071067811865476f));
                    else if (base_ep == 2) t += Res[(long long)rr * ldc + cc];
                    if (rnd) t = tf32r(t);
                    v[j] = t;
                }
                if (outh) {
                    __half2 p;
                    p.x = __float2half(v[0]);
                    p.y = __float2half(v[1]);
                    *(__half2*)&Ch[(long long)rr * ldc + c0] = p;
                } else {
                    *(float2*)&C[(long long)rr * ldc + c0] = make_float2(v[0], v[1]);
                }
            }
        }
    }
}

// ---------------- fused attention (tf32; writes fp16 o) ----------------
#define SK 68
#define SP 204
#define SM_Q  0
#define SM_K  (SM_Q + 64*SK)
#define SM_P  (SM_K + 200*SK)
#define SM_V  (SM_P + 64*SP)
#define SM_TOT ((SM_V + 64*SP)*4)

__global__ __launch_bounds__(256, 1) void fused_attn(
    const float* __restrict__ qkv, const float* __restrict__ lm, __half* __restrict__ o)
{
    extern __shared__ float sm[];
    float* Qs = sm + SM_Q;
    float* Ks = sm + SM_K;
    float* Ps = sm + SM_P;
    float* Vt = sm + SM_V;

    int tid = threadIdx.x;
    int w = tid >> 5, lane = tid & 31;
    int g = lane >> 2, tig = lane & 3;
    int qi = blockIdx.x, h = blockIdx.y, bt = blockIdx.z;
    int q0 = qi * 64;
    const float* base = qkv + (long)bt * NT * 3 * D + h * HD;

    {
        int r = tid >> 2;
        int c = (tid & 3) * 16;
        int q = q0 + r;
        if (q < NT) {
            const float* p = base + (long)q * 3 * D + c;
            #pragma unroll
            for (int j = 0; j < 4; j++)
                *(float4*)&Qs[r*SK + c + j*4] = *(const float4*)(p + j * 4);
        } else {
            #pragma unroll
            for (int j = 0; j < 16; j++) Qs[r*SK + c + j] = 0.f;
        }
    }
    {
        int c = (tid & 3) * 16;
        for (int r = tid >> 2; r < NT; r += 64) {
            const float* p = base + (long)r * 3 * D + D + c;
            #pragma unroll
            for (int j = 0; j < 4; j++)
                *(float4*)&Ks[r*SK + c + j*4] = *(const float4*)(p + j * 4);
        }
        for (int i = tid; i < 3 * 64; i += 256)
            Ks[(197 + i / 64) * SK + (i % 64)] = 0.f;
    }
    {
        int c4 = (tid & 15) * 4;
        for (int m = tid >> 4; m < NT; m += 16) {
            float4 v = *(const float4*)(base + (long)m * 3 * D + 2 * D + c4);
            Vt[(c4 + 0) * SP + m] = v.x;
            Vt[(c4 + 1) * SP + m] = v.y;
            Vt[(c4 + 2) * SP + m] = v.z;
            Vt[(c4 + 3) * SP + m] = v.w;
        }
        for (int i = tid; i < 64 * 7; i += 256)
            Vt[(i / 7) * SP + 197 + (i % 7)] = 0.f;
    }
    __syncthreads();

    {
        int wm = w & 3;
        int wn = w >> 2;
        int nt0 = wn ? 13 : 0, nt1 = wn ? 25 : 13;
        for (int nt = nt0; nt < nt1; nt++) {
            float c[4] = {0.f, 0.f, 0.f, 0.f};
            #pragma unroll
            for (int kk = 0; kk < 64; kk += 8) {
                unsigned a[4], b[2];
                int ra = wm * 16 + g;
                a[0] = __float_as_uint(Qs[ra*SK + kk + tig]);
                a[1] = __float_as_uint(Qs[(ra + 8)*SK + kk + tig]);
                a[2] = __float_as_uint(Qs[ra*SK + kk + tig + 4]);
                a[3] = __float_as_uint(Qs[(ra + 8)*SK + kk + tig + 4]);
                int rb = nt * 8 + g;
                b[0] = __float_as_uint(Ks[rb*SK + kk + tig]);
                b[1] = __float_as_uint(Ks[rb*SK + kk + tig + 4]);
                mma8(c, a, b);
            }
            int rm = wm * 16 + g, cn = nt * 8 + tig * 2;
            Ps[rm*SP + cn] = c[0];       Ps[rm*SP + cn + 1] = c[1];
            Ps[(rm+8)*SP + cn] = c[2];   Ps[(rm+8)*SP + cn + 1] = c[3];
        }
    }
    __syncthreads();

    {
        for (int rr = 0; rr < 8; rr++) {
            int r = (w << 3) + rr;
            int q = q0 + r;
            if (q < NT) {
                const float* lmr = lm + ((long)bt * NT + q) * NT;
                float mx = -1e30f;
                for (int k = lane; k < NT; k += 32) mx = fmaxf(mx, Ps[r*SP + k]);
                #pragma unroll
                for (int s = 16; s > 0; s >>= 1) mx = fmaxf(mx, __shfl_xor_sync(0xffffffffu, mx, s));
                float sum = 0.f;
                for (int k = lane; k < NT; k += 32) {
                    float e = expf(0.125f * (Ps[r*SP + k] - mx));
                    Ps[r*SP + k] = e;
                    sum += e;
                }
                #pragma unroll
                for (int s = 16; s > 0; s >>= 1) sum += __shfl_xor_sync(0xffffffffu, sum, s);
                float inv = 1.0f / sum;
                for (int k = lane; k < 204; k += 32) {
                    float p = (k < NT) ? tf32r(Ps[r*SP + k] * inv * lmr[k]) : 0.f;
                    Ps[r*SP + k] = p;
                }
            } else {
                for (int k = lane; k < 204; k += 32) Ps[r*SP + k] = 0.f;
            }
        }
    }
    __syncthreads();

    {
        int wmA = w >> 1;
        int wnA = w & 1;
        float acc[4][4];
        #pragma unroll
        for (int nt = 0; nt < 4; nt++)
            #pragma unroll
            for (int i = 0; i < 4; i++) acc[nt][i] = 0.f;

        for (int kk = 0; kk < 200; kk += 8) {
            unsigned a[4], b[4][2];
            int ra = wmA * 16 + g;
            a[0] = __float_as_uint(Ps[ra*SP + kk + tig]);
            a[1] = __float_as_uint(Ps[(ra + 8)*SP + kk + tig]);
            a[2] = __float_as_uint(Ps[ra*SP + kk + tig + 4]);
            a[3] = __float_as_uint(Ps[(ra + 8)*SP + kk + tig + 4]);
            #pragma unroll
            for (int nt = 0; nt < 4; nt++) {
                int rb = wnA * 32 + nt * 8 + g;
                b[nt][0] = __float_as_uint(Vt[rb*SP + kk + tig]);
                b[nt][1] = __float_as_uint(Vt[rb*SP + kk + tig + 4]);
            }
            #pragma unroll
            for (int nt = 0; nt < 4; nt++) mma8(acc[nt], a, b[nt]);
        }

        #pragma unroll
        for (int nt = 0; nt < 4; nt++) {
            int cn = wnA * 32 + nt * 8 + tig * 2;
            #pragma unroll
            for (int i = 0; i < 2; i++) {
                int q = q0 + wmA * 16 + g + i * 8;
                if (q >= NT) continue;
                __half* op = o + ((long)bt * NT + q) * D + h * HD + cn;
                __half2 p;
                p.x = __float2half(acc[nt][i * 2]);
                p.y = __float2half(acc[nt][i * 2 + 1]);
                *(__half2*)op = p;
            }
        }
    }
}

// ---------------- fused scatter(+residual) + LayerNorm2 -> y (fp32), xn2h (fp16) ----------------
__global__ void scatter_ln(const float* __restrict__ x, const float* __restrict__ op,
                           const float* __restrict__ g, const float* __restrict__ be,
                           float* __restrict__ y, __half* __restrict__ xn2h) {
    int row = blockIdx.x;
    int tid = threadIdx.x;
    int p = row % ST;
    int b = row / ST;
    float v[3];
    #pragma unroll
    for (int c = 0; c < 3; c++) {
        int d = tid + c * 256;
        float add;
        if (p == 0) {
            float s = 0.f;
            #pragma unroll
            for (int t = 0; t < TT; t++)
                s += op[((long)((b * TT + t) * NT)) * D + d];
            add = s * (1.0f / TT);
        } else {
            int q = p - 1;
            int hw = q / TT, t = q % TT;
            add = op[((long)((b * TT + t) * NT + 1 + hw)) * D + d];
        }
        v[c] = x[(long)row * D + d] + add;
        y[(long)row * D + d] = v[c];
    }
    __shared__ float red[256];
    red[tid] = v[0] + v[1] + v[2];
    __syncthreads();
    for (int o = 128; o > 0; o >>= 1) { if (tid < o) red[tid] += red[tid + o]; __syncthreads(); }
    float mean = red[0] * (1.0f / D);
    __syncthreads();
    float d0 = v[0] - mean, d1 = v[1] - mean, d2 = v[2] - mean;
    red[tid] = d0*d0 + d1*d1 + d2*d2;
    __syncthreads();
    for (int o = 128; o > 0; o >>= 1) { if (tid < o) red[tid] += red[tid + o]; __syncthreads(); }
    float rs = rsqrtf(red[0] * (1.0f / D) + 1e-5f);
    __half* yr = xn2h + (long)row * D;
    yr[tid]       = __float2half(d0 * rs * g[tid]       + be[tid]);
    yr[tid + 256] = __float2half(d1 * rs * g[tid + 256] + be[tid + 256]);
    yr[tid + 512] = __float2half(d2 * rs * g[tid + 512] + be[tid + 512]);
}

// ---------------- launcher ----------------
extern "C" void kernel_launch(void* const* d_in, const int* in_sizes, int n_in,
                              void* d_out, int out_size) {
    const float* x    = (const float*)d_in[0];
    const float* Wmq  = (const float*)d_in[1];
    const float* bmq  = (const float*)d_in[2];
    const float* Wmk  = (const float*)d_in[3];
    const float* bmk  = (const float*)d_in[4];
    const float* g1   = (const float*)d_in[5];
    const float* be1  = (const float*)d_in[6];
    const float* Wqkv = (const float*)d_in[7];
    const float* Wpr  = (const float*)d_in[8];
    const float* bpr  = (const float*)d_in[9];
    const float* g2   = (const float*)d_in[10];
    const float* be2  = (const float*)d_in[11];
    const float* Wf1  = (const float*)d_in[12];
    const float* bf1  = (const float*)d_in[13];
    const float* Wf2  = (const float*)d_in[14];
    const float* bf2  = (const float*)d_in[15];

    float* out = (float*)d_out;
    float* y   = out;
    float* lm  = out + YSZ;

    float *qmk, *bqk, *qkv, *op;
    __half *xth, *xnh, *oh, *xn2h, *hh, *wqkh, *wqkvh, *wprh, *wf1h, *wf2h;
    cudaGetSymbolAddress((void**)&xth,  g_xth);
    cudaGetSymbolAddress((void**)&xnh,  g_xnh);
    cudaGetSymbolAddress((void**)&qmk,  g_qmk);
    cudaGetSymbolAddress((void**)&bqk,  g_bqk);
    cudaGetSymbolAddress((void**)&qkv,  g_qkv);
    cudaGetSymbolAddress((void**)&oh,   g_oh);
    cudaGetSymbolAddress((void**)&op,   g_op);
    cudaGetSymbolAddress((void**)&xn2h, g_xn2h);
    cudaGetSymbolAddress((void**)&hh,   g_hh);
    cudaGetSymbolAddress((void**)&wqkh, g_wqkh);
    cudaGetSymbolAddress((void**)&wqkvh,g_wqkvh);
    cudaGetSymbolAddress((void**)&wprh, g_wprh);
    cudaGetSymbolAddress((void**)&wf1h, g_wf1h);
    cudaGetSymbolAddress((void**)&wf2h, g_wf2h);

    static int smem_set = 0;
    if (!smem_set) {
        cudaFuncSetAttribute(fused_attn, cudaFuncAttributeMaxDynamicSharedMemorySize, SM_TOT);
        cudaFuncSetAttribute(gemm_tf32, cudaFuncAttributeMaxDynamicSharedMemorySize, SMEM_G);
        cudaFuncSetAttribute(gemm_h16,  cudaFuncAttributeMaxDynamicSharedMemorySize, SMEM_H);
        smem_set = 1;
    }

    int gy  = (MXT + 127) / 128;   // 99
    int gy2 = (MY  + 127) / 128;   // 99

    // 0) weight prep (fp16 copies; fp32 mask biases)
    round_weights<<<(14 * D * D + 255) / 256, 256>>>(Wqkv, Wpr, Wf1, Wf2, Wmq, Wmk, bmq, bmk);

    // 1) gather + LN1 (fp16 outputs)
    gather_ln<<<MXT, 256>>>(x, g1, be1, xth, xnh);

    // 2) fused mask projections [qm|km] (fp16 MMA; fp32 out, tf32-rounded for lm GEMM)
    gemm_h16<<<dim3((2*D)/128, gy), 256, SMEM_H>>>(xth, wqkh, bqk, nullptr, qmk, nullptr,
                                                   MXT, 2*D, D, D, D, 2*D, 0 | 8);

    // 3) lm logits (batched tf32) + fused sigmoid w/ forced [0,0]=100
    gemm_tf32<<<dim3(2, 2, BT), 256, SMEM_G>>>(qmk, qmk + D, nullptr, nullptr, lm, NT, NT, D,
                                               2*D, 2*D, NT,
                                               1, 0, 0, (long long)NT*2*D, (long long)NT*2*D,
                                               (long long)NT*NT, 1.0f, 3);

    // 4) QKV projection (fp16 MMA; fp32 out, tf32-rounded for attention)
    gemm_h16<<<dim3((3*D)/128, gy), 256, SMEM_H>>>(xnh, wqkvh, nullptr, nullptr, qkv, nullptr,
                                                   MXT, 3*D, D, D, D, 3*D, 0 | 8);

    // 5) fused attention (tf32; fp16 o out)
    fused_attn<<<dim3(4, NHD, BT), 256, SM_TOT>>>(qkv, lm, oh);

    // 6) output projection (fp16), scatter + LN2 (fp16 xn2)
    gemm_h16<<<dim3(D/128, gy), 256, SMEM_H>>>(oh, wprh, bpr, nullptr, op, nullptr,
                                               MXT, D, D, D, D, D, 0);
    scatter_ln<<<MY, 256>>>(x, op, g2, be2, y, xn2h);

    // 7) MLP fp16: fc1(+gelu -> fp16 h) -> fc2(+residual into y)
    gemm_h16<<<dim3(DH/128, gy2), 256, SMEM_H>>>(xn2h, wf1h, bf1, nullptr, nullptr, hh,
                                                 MY, DH, D, D, D, DH, 1 | 16);
    gemm_h16<<<dim3(D/128, gy2), 256, SMEM_H>>>(hh, wf2h, bf2, y, y, nullptr,
                                                MY, D, DH, DH, DH, D, 2);
}

// round 14
// speedup vs baseline: 1.6521x; 1.0699x over previous
#include <cuda_runtime.h>
#include <cuda_fp16.h>
#include <math.h>

// ---------------- problem constants ----------------
#define D    768
#define DH   3072
#define BB   8
#define TT   8
#define NT   197
#define BT   64
#define NHD  12
#define HD   64
#define ST   1569
#define MXT  (BT*NT)        // 12608
#define MY   (BB*ST)        // 12552
#define YSZ  (MY*D)
#define LMSZ (BT*NT*NT)

#define GS   4
#define SMEM_G (GS*2*128*20*4)   // 81920 (tf32 stages)
#define SMEM_H (GS*2*128*40*2)   // 81920 (fp16 stages)

// ---------------- scratch ----------------
__device__ __half g_xth [MXT*D];
__device__ __half g_xnh [MXT*D];
__device__ float  g_qmk [MXT*2*D];
__device__ float  g_bqk [2*D];
__device__ __half g_qkvh[MXT*3*D];
__device__ __half g_oh  [MXT*D];
__device__ float  g_op  [MXT*D];
__device__ __half g_xn2h[MY*D];
__device__ __half g_hh  [MY*DH];
__device__ __half g_wqkh [2*D*D];
__device__ __half g_wqkvh[3*D*D];
__device__ __half g_wprh [D*D];
__device__ __half g_wf1h [DH*D];
__device__ __half g_wf2h [D*DH];

// ---------------- helpers ----------------
__device__ __forceinline__ float tf32r(float x) {
    unsigned r;
    asm("cvt.rna.tf32.f32 %0, %1;" : "=r"(r) : "f"(x));
    return __uint_as_float(r);
}

__device__ __forceinline__ void mma8(float* c, const unsigned* a, const unsigned* b) {
    asm volatile(
        "mma.sync.aligned.m16n8k8.row.col.f32.tf32.tf32.f32 "
        "{%0,%1,%2,%3}, {%4,%5,%6,%7}, {%8,%9}, {%0,%1,%2,%3};"
        : "+f"(c[0]), "+f"(c[1]), "+f"(c[2]), "+f"(c[3])
        : "r"(a[0]), "r"(a[1]), "r"(a[2]), "r"(a[3]), "r"(b[0]), "r"(b[1]));
}

__device__ __forceinline__ void mma16h(float* c, const unsigned* a, const unsigned* b) {
    asm volatile(
        "mma.sync.aligned.m16n8k16.row.col.f32.f16.f16.f32 "
        "{%0,%1,%2,%3}, {%4,%5,%6,%7}, {%8,%9}, {%0,%1,%2,%3};"
        : "+f"(c[0]), "+f"(c[1]), "+f"(c[2]), "+f"(c[3])
        : "r"(a[0]), "r"(a[1]), "r"(a[2]), "r"(a[3]), "r"(b[0]), "r"(b[1]));
}

__device__ __forceinline__ void ldsm_x4(unsigned* r, unsigned addr) {
    asm volatile("ldmatrix.sync.aligned.m8n8.x4.shared.b16 {%0,%1,%2,%3}, [%4];"
        : "=r"(r[0]), "=r"(r[1]), "=r"(r[2]), "=r"(r[3]) : "r"(addr));
}

__device__ __forceinline__ void cpa16(unsigned dst, const void* src, bool p) {
    asm volatile("cp.async.cg.shared.global [%0], [%1], 16, %2;"
        :: "r"(dst), "l"(src), "r"(p ? 16 : 0));
}
#define CP_COMMIT asm volatile("cp.async.commit_group;")
template<int N> __device__ __forceinline__ void cp_wait() {
    asm volatile("cp.async.wait_group %0;" :: "n"(N));
}

// ---------------- merged weight prep (fp16) ----------------
__global__ void round_weights(const float* __restrict__ Wqkv, const float* __restrict__ Wpr,
                              const float* __restrict__ Wf1, const float* __restrict__ Wf2,
                              const float* __restrict__ Wmq, const float* __restrict__ Wmk,
                              const float* __restrict__ bmq, const float* __restrict__ bmk) {
    const int DD = D * D;
    int i = blockIdx.x * blockDim.x + threadIdx.x;
    if (i < 3 * DD)        g_wqkvh[i]          = __float2half(Wqkv[i]);
    else if (i < 4 * DD)   g_wprh[i - 3 * DD]  = __float2half(Wpr[i - 3 * DD]);
    else if (i < 8 * DD)   g_wf1h[i - 4 * DD]  = __float2half(Wf1[i - 4 * DD]);
    else if (i < 12 * DD)  g_wf2h[i - 8 * DD]  = __float2half(Wf2[i - 8 * DD]);
    else if (i < 13 * DD)  g_wqkh[i - 12 * DD] = __float2half(Wmq[i - 12 * DD]);
    else if (i < 14 * DD)  g_wqkh[DD + i - 13 * DD] = __float2half(Wmk[i - 13 * DD]);
    if (i < D) g_bqk[i] = bmq[i];
    else if (i < 2 * D) g_bqk[i] = bmk[i - D];
}

// ---------------- fused gather + LayerNorm1 -> xth, xnh (fp16) ----------------
__global__ void gather_ln(const float* __restrict__ x, const float* __restrict__ g,
                          const float* __restrict__ be,
                          __half* __restrict__ xth, __half* __restrict__ xnh) {
    int row = blockIdx.x;
    int tid = threadIdx.x;
    int n  = row % NT;
    int bt = row / NT;
    int b = bt / TT, t = bt % TT;
    int src = (n == 0) ? (b * ST) : (b * ST + 1 + (n - 1) * TT + t);
    const float* xr = x + (long)src * D;
    float v0 = xr[tid], v1 = xr[tid + 256], v2 = xr[tid + 512];
    __half* xtr = xth + (long)row * D;
    xtr[tid] = __float2half(v0); xtr[tid + 256] = __float2half(v1); xtr[tid + 512] = __float2half(v2);

    __shared__ float red[256];
    red[tid] = v0 + v1 + v2;
    __syncthreads();
    for (int o = 128; o > 0; o >>= 1) { if (tid < o) red[tid] += red[tid + o]; __syncthreads(); }
    float mean = red[0] * (1.0f / D);
    __syncthreads();
    float d0 = v0 - mean, d1 = v1 - mean, d2 = v2 - mean;
    red[tid] = d0*d0 + d1*d1 + d2*d2;
    __syncthreads();
    for (int o = 128; o > 0; o >>= 1) { if (tid < o) red[tid] += red[tid + o]; __syncthreads(); }
    float rs = rsqrtf(red[0] * (1.0f / D) + 1e-5f);
    __half* yr = xnh + (long)row * D;
    yr[tid]       = __float2half(d0 * rs * g[tid]       + be[tid]);
    yr[tid + 256] = __float2half(d1 * rs * g[tid + 256] + be[tid + 256]);
    yr[tid + 512] = __float2half(d2 * rs * g[tid + 512] + be[tid + 512]);
}

// ---------------- tf32 GEMM — lm logits only ----------------
// ep low 3 bits: 3=sigmoid w/ forced [0,0]=100
__global__ __launch_bounds__(256, 2) void gemm_tf32(
    const float* __restrict__ A, const float* __restrict__ B,
    const float* __restrict__ bias, const float* __restrict__ Res,
    float* __restrict__ C, int M, int N, int K,
    int lda, int ldb, int ldc,
    int inner, int sAi, int sBi, long long sAo, long long sBo, long long sC,
    float alpha, int ep)
{
    extern __shared__ __align__(16) float dyn[];

    int tid  = threadIdx.x;
    int warp = tid >> 5, lane = tid & 31;
    int g = lane >> 2, tig = lane & 3;
    int wm = warp >> 2;
    int wn = warp & 3;
    int m0 = blockIdx.y * 128, n0 = blockIdx.x * 128;

    const float* Ab = A;
    const float* Bb = B;
    float* Cb = C;
    if (sC) {
        int z = blockIdx.z;
        int zo = z / inner, zi = z % inner;
        Ab += (long long)zo * sAo + (long long)zi * sAi;
        Bb += (long long)zo * sBo + (long long)zi * sBi;
        Cb += (long long)z * sC;
    }

    int ldrow = tid >> 1;
    int ldcol = (tid & 1) * 8;
    bool aok = (m0 + ldrow) < M;
    bool bok = (n0 + ldrow) < N;
    const float* Ap = Ab + (long long)(m0 + ldrow) * lda + ldcol;
    const float* Bp = Bb + (long long)(n0 + ldrow) * ldb + ldcol;

    unsigned smB = (unsigned)__cvta_generic_to_shared(dyn);
    const unsigned STG = 128 * 20 * 4;
    unsigned aSt = smB + (ldrow * 20 + ldcol) * 4;
    unsigned bSt = smB + GS * STG + (ldrow * 20 + ldcol) * 4;

    int arow = lane & 15;
    int acol = (lane >> 4) * 4;
    int brow = (lane & 7) + ((lane & 16) >> 1);
    int bcol = ((lane >> 3) & 1) * 4;
    unsigned aAddr = smB + ((wm * 64 + arow) * 20 + acol) * 4;
    unsigned bAddr = smB + GS * STG + ((wn * 32 + brow) * 20 + bcol) * 4;

    float acc[4][4][4];
    #pragma unroll
    for (int mt = 0; mt < 4; mt++)
        #pragma unroll
        for (int nt = 0; nt < 4; nt++)
            #pragma unroll
            for (int i = 0; i < 4; i++) acc[mt][nt][i] = 0.f;

    int nkt = K >> 4;

    #pragma unroll
    for (int s = 0; s < GS - 1; s++) {
        bool has = s < nkt;
        cpa16(aSt + s * STG,      Ap + s * 16,     aok && has);
        cpa16(aSt + s * STG + 16, Ap + s * 16 + 4, aok && has);
        cpa16(bSt + s * STG,      Bp + s * 16,     bok && has);
        cpa16(bSt + s * STG + 16, Bp + s * 16 + 4, bok && has);
        CP_COMMIT;
    }

#define LOADFRAG(aB, bB, kko) do { \
        ldsm_x4(fa[0], (aB) + 0 * 1280 + (kko)); \
        ldsm_x4(fa[1], (aB) + 1 * 1280 + (kko)); \
        ldsm_x4(fa[2], (aB) + 2 * 1280 + (kko)); \
        ldsm_x4(fa[3], (aB) + 3 * 1280 + (kko)); \
        ldsm_x4(fb2[0], (bB) + 0 * 1280 + (kko)); \
        ldsm_x4(fb2[1], (bB) + 1 * 1280 + (kko)); \
    } while (0)
#define MMA_ALL do { \
        _Pragma("unroll") \
        for (int mt = 0; mt < 4; mt++) \
            _Pragma("unroll") \
            for (int nt = 0; nt < 4; nt++) { \
                unsigned bb[2] = { fb2[nt >> 1][(nt & 1) * 2], fb2[nt >> 1][(nt & 1) * 2 + 1] }; \
                mma8(acc[mt][nt], fa[mt], bb); \
            } \
    } while (0)

    for (int kt = 0; kt < nkt; kt++) {
        cp_wait<GS - 2>();
        __syncthreads();
        int cur = kt & (GS - 1);
        unsigned aB = aAddr + cur * STG;
        unsigned bB = bAddr + cur * STG;

        {
            int pf = kt + GS - 1;
            bool has = pf < nkt;
            int ps = pf & (GS - 1);
            cpa16(aSt + ps * STG,      Ap + pf * 16,     aok && has);
            cpa16(aSt + ps * STG + 16, Ap + pf * 16 + 4, aok && has);
            cpa16(bSt + ps * STG,      Bp + pf * 16,     bok && has);
            cpa16(bSt + ps * STG + 16, Bp + pf * 16 + 4, bok && has);
            CP_COMMIT;
        }

        unsigned fa[4][4], fb2[2][4];
        LOADFRAG(aB, bB, 0);
        MMA_ALL;
        LOADFRAG(aB, bB, 32);
        MMA_ALL;
    }
#undef LOADFRAG
#undef MMA_ALL

    int base_ep = ep & 7;
    bool rnd = (ep & 8) != 0;
    bool v2ok = (ldc & 1) == 0;

    #pragma unroll
    for (int mt = 0; mt < 4; mt++) {
        int r0 = m0 + wm * 64 + mt * 16 + g;
        #pragma unroll
        for (int nt = 0; nt < 4; nt++) {
            int c0 = n0 + wn * 32 + nt * 8 + tig * 2;
            #pragma unroll
            for (int i = 0; i < 2; i++) {
                int rr = r0 + i * 8;
                if (rr >= M) continue;
                float v[2];
                #pragma unroll
                for (int j = 0; j < 2; j++) {
                    int cc = c0 + j;
                    float t = acc[mt][nt][i * 2 + j] * alpha;
                    if (base_ep == 3) {
                        if (rr == 0 && cc == 0) t = 100.0f;
                        t = 1.0f / (1.0f + expf(-t));
                    } else {
                        if (bias) t += bias[cc];
                        if (base_ep == 1) t = 0.5f * t * (1.0f + erff(t * 0.7071067811865476f));
                        else if (base_ep == 2) t += Res[(long long)rr * ldc + cc];
                    }
                    if (rnd) t = tf32r(t);
                    v[j] = t;
                }
                if (v2ok && c0 + 1 < N) {
                    *(float2*)&Cb[(long long)rr * ldc + c0] = make_float2(v[0], v[1]);
                } else {
                    if (c0 < N)     Cb[(long long)rr * ldc + c0] = v[0];
                    if (c0 + 1 < N) Cb[(long long)rr * ldc + c0 + 1] = v[1];
                }
            }
        }
    }
}

// ---------------- fp16 GEMM: m16n8k16, K-tile=32 halves ----------------
// ep low 3 bits: 0=+bias 1=+bias,gelu 2=+bias,+Res ; bit3 (8): round out tf32 ; bit4 (16): out fp16 to Ch
__global__ __launch_bounds__(256, 2) void gemm_h16(
    const __half* __restrict__ A, const __half* __restrict__ B,
    const float* __restrict__ bias, const float* __restrict__ Res,
    float* __restrict__ C, __half* __restrict__ Ch,
    int M, int N, int K, int lda, int ldb, int ldc, int ep)
{
    extern __shared__ __align__(16) float dyn[];

    int tid  = threadIdx.x;
    int warp = tid >> 5, lane = tid & 31;
    int g = lane >> 2, tig = lane & 3;
    int wm = warp >> 2;
    int wn = warp & 3;
    int m0 = blockIdx.y * 128, n0 = blockIdx.x * 128;

    int lrow = tid >> 1;
    int lch  = (tid & 1) * 2;
    bool aok = (m0 + lrow) < M;
    bool bok = (n0 + lrow) < N;
    const __half* Ap = A + (long long)(m0 + lrow) * lda + lch * 8;
    const __half* Bp = B + (long long)(n0 + lrow) * ldb + lch * 8;

    unsigned smB = (unsigned)__cvta_generic_to_shared(dyn);
    const unsigned STG = 128 * 40 * 2;
    unsigned aSt = smB + lrow * 80 + lch * 16;
    unsigned bSt = smB + GS * STG + lrow * 80 + lch * 16;

    int arow = lane & 15;
    int acolB = (lane >> 4) * 16;
    int brow = (lane & 7) + ((lane & 16) >> 1);
    int bcolB = ((lane >> 3) & 1) * 16;
    unsigned aAddr = smB + (wm * 64 + arow) * 80 + acolB;
    unsigned bAddr = smB + GS * STG + (wn * 32 + brow) * 80 + bcolB;

    float acc[4][4][4];
    #pragma unroll
    for (int mt = 0; mt < 4; mt++)
        #pragma unroll
        for (int nt = 0; nt < 4; nt++)
            #pragma unroll
            for (int i = 0; i < 4; i++) acc[mt][nt][i] = 0.f;

    int nkt = K >> 5;

    #pragma unroll
    for (int s = 0; s < GS - 1; s++) {
        bool has = s < nkt;
        cpa16(aSt + s * STG,      Ap + s * 32,     aok && has);
        cpa16(aSt + s * STG + 16, Ap + s * 32 + 8, aok && has);
        cpa16(bSt + s * STG,      Bp + s * 32,     bok && has);
        cpa16(bSt + s * STG + 16, Bp + s * 32 + 8, bok && has);
        CP_COMMIT;
    }

#define LOADFRAGH(aB, bB, kko) do { \
        ldsm_x4(fa[0], (aB) + 0 * 1280 + (kko)); \
        ldsm_x4(fa[1], (aB) + 1 * 1280 + (kko)); \
        ldsm_x4(fa[2], (aB) + 2 * 1280 + (kko)); \
        ldsm_x4(fa[3], (aB) + 3 * 1280 + (kko)); \
        ldsm_x4(fb2[0], (bB) + 0 * 1280 + (kko)); \
        ldsm_x4(fb2[1], (bB) + 1 * 1280 + (kko)); \
    } while (0)
#define MMAH_ALL do { \
        _Pragma("unroll") \
        for (int mt = 0; mt < 4; mt++) \
            _Pragma("unroll") \
            for (int nt = 0; nt < 4; nt++) { \
                unsigned bb[2] = { fb2[nt >> 1][(nt & 1) * 2], fb2[nt >> 1][(nt & 1) * 2 + 1] }; \
                mma16h(acc[mt][nt], fa[mt], bb); \
            } \
    } while (0)

    for (int kt = 0; kt < nkt; kt++) {
        cp_wait<GS - 2>();
        __syncthreads();
        int cur = kt & (GS - 1);
        unsigned aB = aAddr + cur * STG;
        unsigned bB = bAddr + cur * STG;

        {
            int pf = kt + GS - 1;
            bool has = pf < nkt;
            int ps = pf & (GS - 1);
            cpa16(aSt + ps * STG,      Ap + pf * 32,     aok && has);
            cpa16(aSt + ps * STG + 16, Ap + pf * 32 + 8, aok && has);
            cpa16(bSt + ps * STG,      Bp + pf * 32,     bok && has);
            cpa16(bSt + ps * STG + 16, Bp + pf * 32 + 8, bok && has);
            CP_COMMIT;
        }

        unsigned fa[4][4], fb2[2][4];
        LOADFRAGH(aB, bB, 0);
        MMAH_ALL;
        LOADFRAGH(aB, bB, 32);
        MMAH_ALL;
    }
#undef LOADFRAGH
#undef MMAH_ALL

    int base_ep = ep & 7;
    bool rnd = (ep & 8) != 0;
    bool outh = (ep & 16) != 0;

    #pragma unroll
    for (int mt = 0; mt < 4; mt++) {
        int r0 = m0 + wm * 64 + mt * 16 + g;
        #pragma unroll
        for (int nt = 0; nt < 4; nt++) {
            int c0 = n0 + wn * 32 + nt * 8 + tig * 2;
            #pragma unroll
            for (int i = 0; i < 2; i++) {
                int rr = r0 + i * 8;
                if (rr >= M) continue;
                float v[2];
                #pragma unroll
                for (int j = 0; j < 2; j++) {
                    int cc = c0 + j;
                    float t = acc[mt][nt][i * 2 + j];
                    if (bias) t += bias[cc];
                    if (base_ep == 1) t = 0.5f * t * (1.0f + erff(t * 0.7071067811865476f));
                    else if (base_ep == 2) t += Res[(long long)rr * ldc + cc];
                    if (rnd) t = tf32r(t);
                    v[j] = t;
                }
                if (outh) {
                    __half2 p;
                    p.x = __float2half(v[0]);
                    p.y = __float2half(v[1]);
                    *(__half2*)&Ch[(long long)rr * ldc + c0] = p;
                } else {
                    *(float2*)&C[(long long)rr * ldc + c0] = make_float2(v[0], v[1]);
                }
            }
        }
    }
}

// ---------------- fused attention, fp16 MMAs ----------------
#define SKH 72     // Qs/Ks stride (halves)
#define SPH 210    // Ph/Vt stride (halves)
#define SPS 204    // Ps stride (floats)
#define OQ  0                         // Qs: 64*72 halves
#define OK_ (OQ + 64*SKH)             // Ks: 200*72
#define OV  (OK_ + 200*SKH)           // Vt: 64*210
#define OP_ (OV + 64*SPH)             // Ph: 64*210
#define OPS_BYTES (((OP_ + 64*SPH)*2 + 15) & ~15)
#define SM_ATT (OPS_BYTES + 64*SPS*4)   // ~144 KB

__global__ __launch_bounds__(256, 1) void fused_attn(
    const __half* __restrict__ qkv, const float* __restrict__ lm, __half* __restrict__ o)
{
    extern __shared__ char smc[];
    __half* Qs = (__half*)smc + OQ;
    __half* Ks = (__half*)smc + OK_;
    __half* Vt = (__half*)smc + OV;
    __half* Ph = (__half*)smc + OP_;
    float*  Ps = (float*)(smc + OPS_BYTES);

    int tid = threadIdx.x;
    int w = tid >> 5, lane = tid & 31;
    int g = lane >> 2, tig = lane & 3;
    int qi = blockIdx.x, h = blockIdx.y, bt = blockIdx.z;
    int q0 = qi * 64;
    const __half* base = qkv + (long)bt * NT * 3 * D + h * HD;

    // ---- load Q tile (fp16, 64 halves/row) ----
    {
        int r = tid >> 2;
        int c = (tid & 3) * 16;
        int q = q0 + r;
        if (q < NT) {
            const uint4* p = (const uint4*)(base + (long)q * 3 * D + c);
            *(uint4*)&Qs[r * SKH + c]     = p[0];
            *(uint4*)&Qs[r * SKH + c + 8] = p[1];
        } else {
            #pragma unroll
            for (int j = 0; j < 16; j++) Qs[r * SKH + c + j] = __float2half(0.f);
        }
    }
    // ---- load K (197 rows), zero rows 197..199 ----
    {
        int c = (tid & 3) * 16;
        for (int r = tid >> 2; r < NT; r += 64) {
            const uint4* p = (const uint4*)(base + (long)r * 3 * D + D + c);
            *(uint4*)&Ks[r * SKH + c]     = p[0];
            *(uint4*)&Ks[r * SKH + c + 8] = p[1];
        }
        for (int i = tid; i < 3 * 64; i += 256)
            Ks[(197 + i / 64) * SKH + (i % 64)] = __float2half(0.f);
    }
    // ---- load V transposed Vt[d][m], zero cols 197..209 ----
    {
        int c4 = (tid & 15) * 4;
        for (int m = tid >> 4; m < NT; m += 16) {
            const __half* vp = base + (long)m * 3 * D + 2 * D + c4;
            __half2 va = *(const __half2*)vp;
            __half2 vb = *(const __half2*)(vp + 2);
            Vt[(c4 + 0) * SPH + m] = va.x;
            Vt[(c4 + 1) * SPH + m] = va.y;
            Vt[(c4 + 2) * SPH + m] = vb.x;
            Vt[(c4 + 3) * SPH + m] = vb.y;
        }
        for (int i = tid; i < 64 * 13; i += 256)
            Vt[(i / 13) * SPH + 197 + (i % 13)] = __float2half(0.f);
    }
    __syncthreads();

    // ---- S = Q @ K^T (fp16 MMA, fp32 scores to Ps) ----
    {
        int wm = w & 3;
        int wn = w >> 2;
        int nt0 = wn ? 13 : 0, nt1 = wn ? 25 : 13;
        int ra0 = (wm * 16 + g) * SKH;
        for (int nt = nt0; nt < nt1; nt++) {
            float c[4] = {0.f, 0.f, 0.f, 0.f};
            int rb0 = (nt * 8 + g) * SKH;
            #pragma unroll
            for (int kk = 0; kk < 64; kk += 16) {
                unsigned a[4], b[2];
                a[0] = *(const unsigned*)&Qs[ra0 + kk + 2 * tig];
                a[1] = *(const unsigned*)&Qs[ra0 + 8 * SKH + kk + 2 * tig];
                a[2] = *(const unsigned*)&Qs[ra0 + kk + 2 * tig + 8];
                a[3] = *(const unsigned*)&Qs[ra0 + 8 * SKH + kk + 2 * tig + 8];
                b[0] = *(const unsigned*)&Ks[rb0 + kk + 2 * tig];
                b[1] = *(const unsigned*)&Ks[rb0 + kk + 2 * tig + 8];
                mma16h(c, a, b);
            }
            int rm = wm * 16 + g, cn = nt * 8 + tig * 2;
            Ps[rm * SPS + cn] = c[0];         Ps[rm * SPS + cn + 1] = c[1];
            Ps[(rm + 8) * SPS + cn] = c[2];   Ps[(rm + 8) * SPS + cn + 1] = c[3];
        }
    }
    __syncthreads();

    // ---- softmax + gate -> Ph (fp16) ----
    {
        for (int rr = 0; rr < 8; rr++) {
            int r = (w << 3) + rr;
            int q = q0 + r;
            if (q < NT) {
                const float* lmr = lm + ((long)bt * NT + q) * NT;
                float mx = -1e30f;
                for (int k = lane; k < NT; k += 32) mx = fmaxf(mx, Ps[r * SPS + k]);
                #pragma unroll
                for (int s = 16; s > 0; s >>= 1) mx = fmaxf(mx, __shfl_xor_sync(0xffffffffu, mx, s));
                float sum = 0.f;
                for (int k = lane; k < NT; k += 32) {
                    float e = expf(0.125f * (Ps[r * SPS + k] - mx));
                    Ps[r * SPS + k] = e;
                    sum += e;
                }
                #pragma unroll
                for (int s = 16; s > 0; s >>= 1) sum += __shfl_xor_sync(0xffffffffu, sum, s);
                float inv = 1.0f / sum;
                for (int k = lane; k < SPH; k += 32) {
                    float p = (k < NT) ? (Ps[r * SPS + k] * inv * lmr[k]) : 0.f;
                    Ph[r * SPH + k] = __float2half(p);
                }
            } else {
                for (int k = lane; k < SPH; k += 32) Ph[r * SPH + k] = __float2half(0.f);
            }
        }
    }
    __syncthreads();

    // ---- O = P @ V (fp16 MMA) ----
    {
        int wmA = w >> 1;
        int wnA = w & 1;
        float acc[4][4];
        #pragma unroll
        for (int nt = 0; nt < 4; nt++)
            #pragma unroll
            for (int i = 0; i < 4; i++) acc[nt][i] = 0.f;

        int ra0 = (wmA * 16 + g) * SPH;
        for (int kk = 0; kk < 208; kk += 16) {
            unsigned a[4], b[4][2];
            a[0] = *(const unsigned*)&Ph[ra0 + kk + 2 * tig];
            a[1] = *(const unsigned*)&Ph[ra0 + 8 * SPH + kk + 2 * tig];
            a[2] = *(const unsigned*)&Ph[ra0 + kk + 2 * tig + 8];
            a[3] = *(const unsigned*)&Ph[ra0 + 8 * SPH + kk + 2 * tig + 8];
            #pragma unroll
            for (int nt = 0; nt < 4; nt++) {
                int rb0 = (wnA * 32 + nt * 8 + g) * SPH;
                b[nt][0] = *(const unsigned*)&Vt[rb0 + kk + 2 * tig];
                b[nt][1] = *(const unsigned*)&Vt[rb0 + kk + 2 * tig + 8];
            }
            #pragma unroll
            for (int nt = 0; nt < 4; nt++) mma16h(acc[nt], a, b[nt]);
        }

        #pragma unroll
        for (int nt = 0; nt < 4; nt++) {
            int cn = wnA * 32 + nt * 8 + tig * 2;
            #pragma unroll
            for (int i = 0; i < 2; i++) {
                int q = q0 + wmA * 16 + g + i * 8;
                if (q >= NT) continue;
                __half* op = o + ((long)bt * NT + q) * D + h * HD + cn;
                __half2 p;
                p.x = __float2half(acc[nt][i * 2]);
                p.y = __float2half(acc[nt][i * 2 + 1]);
                *(__half2*)op = p;
            }
        }
    }
}

// ---------------- fused scatter(+residual) + LayerNorm2 -> y (fp32), xn2h (fp16) ----------------
__global__ void scatter_ln(const float* __restrict__ x, const float* __restrict__ op,
                           const float* __restrict__ g, const float* __restrict__ be,
                           float* __restrict__ y, __half* __restrict__ xn2h) {
    int row = blockIdx.x;
    int tid = threadIdx.x;
    int p = row % ST;
    int b = row / ST;
    float v[3];
    #pragma unroll
    for (int c = 0; c < 3; c++) {
        int d = tid + c * 256;
        float add;
        if (p == 0) {
            float s = 0.f;
            #pragma unroll
            for (int t = 0; t < TT; t++)
                s += op[((long)((b * TT + t) * NT)) * D + d];
            add = s * (1.0f / TT);
        } else {
            int q = p - 1;
            int hw = q / TT, t = q % TT;
            add = op[((long)((b * TT + t) * NT + 1 + hw)) * D + d];
        }
        v[c] = x[(long)row * D + d] + add;
        y[(long)row * D + d] = v[c];
    }
    __shared__ float red[256];
    red[tid] = v[0] + v[1] + v[2];
    __syncthreads();
    for (int o = 128; o > 0; o >>= 1) { if (tid < o) red[tid] += red[tid + o]; __syncthreads(); }
    float mean = red[0] * (1.0f / D);
    __syncthreads();
    float d0 = v[0] - mean, d1 = v[1] - mean, d2 = v[2] - mean;
    red[tid] = d0*d0 + d1*d1 + d2*d2;
    __syncthreads();
    for (int o = 128; o > 0; o >>= 1) { if (tid < o) red[tid] += red[tid + o]; __syncthreads(); }
    float rs = rsqrtf(red[0] * (1.0f / D) + 1e-5f);
    __half* yr = xn2h + (long)row * D;
    yr[tid]       = __float2half(d0 * rs * g[tid]       + be[tid]);
    yr[tid + 256] = __float2half(d1 * rs * g[tid + 256] + be[tid + 256]);
    yr[tid + 512] = __float2half(d2 * rs * g[tid + 512] + be[tid + 512]);
}

// ---------------- launcher ----------------
extern "C" void kernel_launch(void* const* d_in, const int* in_sizes, int n_in,
                              void* d_out, int out_size) {
    const float* x    = (const float*)d_in[0];
    const float* Wmq  = (const float*)d_in[1];
    const float* bmq  = (const float*)d_in[2];
    const float* Wmk  = (const float*)d_in[3];
    const float* bmk  = (const float*)d_in[4];
    const float* g1   = (const float*)d_in[5];
    const float* be1  = (const float*)d_in[6];
    const float* Wqkv = (const float*)d_in[7];
    const float* Wpr  = (const float*)d_in[8];
    const float* bpr  = (const float*)d_in[9];
    const float* g2   = (const float*)d_in[10];
    const float* be2  = (const float*)d_in[11];
    const float* Wf1  = (const float*)d_in[12];
    const float* bf1  = (const float*)d_in[13];
    const float* Wf2  = (const float*)d_in[14];
    const float* bf2  = (const float*)d_in[15];

    float* out = (float*)d_out;
    float* y   = out;
    float* lm  = out + YSZ;

    float *qmk, *bqk, *op;
    __half *xth, *xnh, *qkvh, *oh, *xn2h, *hh, *wqkh, *wqkvh, *wprh, *wf1h, *wf2h;
    cudaGetSymbolAddress((void**)&xth,  g_xth);
    cudaGetSymbolAddress((void**)&xnh,  g_xnh);
    cudaGetSymbolAddress((void**)&qmk,  g_qmk);
    cudaGetSymbolAddress((void**)&bqk,  g_bqk);
    cudaGetSymbolAddress((void**)&qkvh, g_qkvh);
    cudaGetSymbolAddress((void**)&oh,   g_oh);
    cudaGetSymbolAddress((void**)&op,   g_op);
    cudaGetSymbolAddress((void**)&xn2h, g_xn2h);
    cudaGetSymbolAddress((void**)&hh,   g_hh);
    cudaGetSymbolAddress((void**)&wqkh, g_wqkh);
    cudaGetSymbolAddress((void**)&wqkvh,g_wqkvh);
    cudaGetSymbolAddress((void**)&wprh, g_wprh);
    cudaGetSymbolAddress((void**)&wf1h, g_wf1h);
    cudaGetSymbolAddress((void**)&wf2h, g_wf2h);

    static int smem_set = 0;
    if (!smem_set) {
        cudaFuncSetAttribute(fused_attn, cudaFuncAttributeMaxDynamicSharedMemorySize, SM_ATT);
        cudaFuncSetAttribute(gemm_tf32, cudaFuncAttributeMaxDynamicSharedMemorySize, SMEM_G);
        cudaFuncSetAttribute(gemm_h16,  cudaFuncAttributeMaxDynamicSharedMemorySize, SMEM_H);
        smem_set = 1;
    }

    int gy  = (MXT + 127) / 128;   // 99
    int gy2 = (MY  + 127) / 128;   // 99

    // 0) weight prep (fp16)
    round_weights<<<(14 * D * D + 255) / 256, 256>>>(Wqkv, Wpr, Wf1, Wf2, Wmq, Wmk, bmq, bmk);

    // 1) gather + LN1 (fp16 outputs)
    gather_ln<<<MXT, 256>>>(x, g1, be1, xth, xnh);

    // 2) fused mask projections [qm|km] (fp16 MMA; fp32 out tf32-rounded for lm GEMM)
    gemm_h16<<<dim3((2*D)/128, gy), 256, SMEM_H>>>(xth, wqkh, bqk, nullptr, qmk, nullptr,
                                                   MXT, 2*D, D, D, D, 2*D, 0 | 8);

    // 3) lm logits (batched tf32) + fused sigmoid w/ forced [0,0]=100
    gemm_tf32<<<dim3(2, 2, BT), 256, SMEM_G>>>(qmk, qmk + D, nullptr, nullptr, lm, NT, NT, D,
                                               2*D, 2*D, NT,
                                               1, 0, 0, (long long)NT*2*D, (long long)NT*2*D,
                                               (long long)NT*NT, 1.0f, 3);

    // 4) QKV projection (fp16 MMA, fp16 out)
    gemm_h16<<<dim3((3*D)/128, gy), 256, SMEM_H>>>(xnh, wqkvh, nullptr, nullptr, nullptr, qkvh,
                                                   MXT, 3*D, D, D, D, 3*D, 0 | 16);

    // 5) fused attention (fp16 MMAs, fp32 softmax, fp16 o out)
    fused_attn<<<dim3(4, NHD, BT), 256, SM_ATT>>>(qkvh, lm, oh);

    // 6) output projection (fp16), scatter + LN2 (fp16 xn2)
    gemm_h16<<<dim3(D/128, gy), 256, SMEM_H>>>(oh, wprh, bpr, nullptr, op, nullptr,
                                               MXT, D, D, D, D, D, 0);
    scatter_ln<<<MY, 256>>>(x, op, g2, be2, y, xn2h);

    // 7) MLP fp16: fc1(+gelu -> fp16 h) -> fc2(+residual into y)
    gemm_h16<<<dim3(DH/128, gy2), 256, SMEM_H>>>(xn2h, wf1h, bf1, nullptr, nullptr, hh,
                                                 MY, DH, D, D, D, DH, 1 | 16);
    gemm_h16<<<dim3(D/128, gy2), 256, SMEM_H>>>(hh, wf2h, bf2, y, y, nullptr,
                                                MY, D, DH, DH, DH, D, 2);
}

// round 15
// speedup vs baseline: 2.2571x; 1.3662x over previous
#include <cuda_runtime.h>
#include <cuda_fp16.h>
#include <math.h>

// ---------------- problem constants ----------------
#define D    768
#define DH   3072
#define BB   8
#define TT   8
#define NT   197
#define BT   64
#define NHD  12
#define HD   64
#define ST   1569
#define MXT  (BT*NT)        // 12608
#define MY   (BB*ST)        // 12552
#define YSZ  (MY*D)
#define LMSZ (BT*NT*NT)

#define GS   4
#define SMEM_H (GS*2*128*40*2)   // 81920 (fp16 stages)

// ---------------- scratch ----------------
__device__ __half g_xth [MXT*D];
__device__ __half g_xnh [MXT*D];
__device__ __half g_qmkh[MXT*2*D];
__device__ float  g_bqk [2*D];
__device__ __half g_qkvh[MXT*3*D];
__device__ __half g_oh  [MXT*D];
__device__ float  g_op  [MXT*D];
__device__ __half g_xn2h[MY*D];
__device__ __half g_hh  [MY*DH];
__device__ __half g_wqkh [2*D*D];
__device__ __half g_wqkvh[3*D*D];
__device__ __half g_wprh [D*D];
__device__ __half g_wf1h [DH*D];
__device__ __half g_wf2h [D*DH];

// ---------------- helpers ----------------
__device__ __forceinline__ void mma16h(float* c, const unsigned* a, const unsigned* b) {
    asm volatile(
        "mma.sync.aligned.m16n8k16.row.col.f32.f16.f16.f32 "
        "{%0,%1,%2,%3}, {%4,%5,%6,%7}, {%8,%9}, {%0,%1,%2,%3};"
        : "+f"(c[0]), "+f"(c[1]), "+f"(c[2]), "+f"(c[3])
        : "r"(a[0]), "r"(a[1]), "r"(a[2]), "r"(a[3]), "r"(b[0]), "r"(b[1]));
}

__device__ __forceinline__ void ldsm_x4(unsigned* r, unsigned addr) {
    asm volatile("ldmatrix.sync.aligned.m8n8.x4.shared.b16 {%0,%1,%2,%3}, [%4];"
        : "=r"(r[0]), "=r"(r[1]), "=r"(r[2]), "=r"(r[3]) : "r"(addr));
}

__device__ __forceinline__ void cpa16(unsigned dst, const void* src, bool p) {
    asm volatile("cp.async.cg.shared.global [%0], [%1], 16, %2;"
        :: "r"(dst), "l"(src), "r"(p ? 16 : 0));
}
#define CP_COMMIT asm volatile("cp.async.commit_group;")
template<int N> __device__ __forceinline__ void cp_wait() {
    asm volatile("cp.async.wait_group %0;" :: "n"(N));
}

// ---------------- merged weight prep (fp16) ----------------
__global__ void round_weights(const float* __restrict__ Wqkv, const float* __restrict__ Wpr,
                              const float* __restrict__ Wf1, const float* __restrict__ Wf2,
                              const float* __restrict__ Wmq, const float* __restrict__ Wmk,
                              const float* __restrict__ bmq, const float* __restrict__ bmk) {
    const int DD = D * D;
    int i = blockIdx.x * blockDim.x + threadIdx.x;
    if (i < 3 * DD)        g_wqkvh[i]          = __float2half(Wqkv[i]);
    else if (i < 4 * DD)   g_wprh[i - 3 * DD]  = __float2half(Wpr[i - 3 * DD]);
    else if (i < 8 * DD)   g_wf1h[i - 4 * DD]  = __float2half(Wf1[i - 4 * DD]);
    else if (i < 12 * DD)  g_wf2h[i - 8 * DD]  = __float2half(Wf2[i - 8 * DD]);
    else if (i < 13 * DD)  g_wqkh[i - 12 * DD] = __float2half(Wmq[i - 12 * DD]);
    else if (i < 14 * DD)  g_wqkh[DD + i - 13 * DD] = __float2half(Wmk[i - 13 * DD]);
    if (i < D) g_bqk[i] = bmq[i];
    else if (i < 2 * D) g_bqk[i] = bmk[i - D];
}

// ---------------- fused gather + LayerNorm1 -> xth, xnh (fp16) ----------------
__global__ void gather_ln(const float* __restrict__ x, const float* __restrict__ g,
                          const float* __restrict__ be,
                          __half* __restrict__ xth, __half* __restrict__ xnh) {
    int row = blockIdx.x;
    int tid = threadIdx.x;
    int n  = row % NT;
    int bt = row / NT;
    int b = bt / TT, t = bt % TT;
    int src = (n == 0) ? (b * ST) : (b * ST + 1 + (n - 1) * TT + t);
    const float* xr = x + (long)src * D;
    float v0 = xr[tid], v1 = xr[tid + 256], v2 = xr[tid + 512];
    __half* xtr = xth + (long)row * D;
    xtr[tid] = __float2half(v0); xtr[tid + 256] = __float2half(v1); xtr[tid + 512] = __float2half(v2);

    __shared__ float red[256];
    red[tid] = v0 + v1 + v2;
    __syncthreads();
    for (int o = 128; o > 0; o >>= 1) { if (tid < o) red[tid] += red[tid + o]; __syncthreads(); }
    float mean = red[0] * (1.0f / D);
    __syncthreads();
    float d0 = v0 - mean, d1 = v1 - mean, d2 = v2 - mean;
    red[tid] = d0*d0 + d1*d1 + d2*d2;
    __syncthreads();
    for (int o = 128; o > 0; o >>= 1) { if (tid < o) red[tid] += red[tid + o]; __syncthreads(); }
    float rs = rsqrtf(red[0] * (1.0f / D) + 1e-5f);
    __half* yr = xnh + (long)row * D;
    yr[tid]       = __float2half(d0 * rs * g[tid]       + be[tid]);
    yr[tid + 256] = __float2half(d1 * rs * g[tid + 256] + be[tid + 256]);
    yr[tid + 512] = __float2half(d2 * rs * g[tid + 512] + be[tid + 512]);
}

// ---------------- fp16 GEMM: m16n8k16, K-tile=32 halves, optional batch ----------------
// A: MxK f16 (lda), B: NxK f16 (ldb). Batch via blockIdx.z when sC != 0.
// ep low 3 bits: 0=+bias 1=+bias,gelu 2=+bias,+Res 3=sigmoid w/ forced [0,0]=100
// bit4 (16): out fp16 to Ch (else fp32 to C)
__global__ __launch_bounds__(256, 2) void gemm_h16(
    const __half* __restrict__ A, const __half* __restrict__ B,
    const float* __restrict__ bias, const float* __restrict__ Res,
    float* __restrict__ C, __half* __restrict__ Ch,
    int M, int N, int K, int lda, int ldb, int ldc,
    long long sAo, long long sBo, long long sC, int ep)
{
    extern __shared__ __align__(16) float dyn[];

    int tid  = threadIdx.x;
    int warp = tid >> 5, lane = tid & 31;
    int g = lane >> 2, tig = lane & 3;
    int wm = warp >> 2;
    int wn = warp & 3;
    int m0 = blockIdx.y * 128, n0 = blockIdx.x * 128;

    const __half* Ab = A;
    const __half* Bb = B;
    float* Cb = C;
    __half* Chb = Ch;
    if (sC) {
        long long z = blockIdx.z;
        Ab += z * sAo;
        Bb += z * sBo;
        if (C)  Cb  += z * sC;
        if (Ch) Chb += z * sC;
    }

    int lrow = tid >> 1;
    int lch  = (tid & 1) * 2;
    bool aok = (m0 + lrow) < M;
    bool bok = (n0 + lrow) < N;
    const __half* Ap = Ab + (long long)(m0 + lrow) * lda + lch * 8;
    const __half* Bp = Bb + (long long)(n0 + lrow) * ldb + lch * 8;

    unsigned smB = (unsigned)__cvta_generic_to_shared(dyn);
    const unsigned STG = 128 * 40 * 2;
    unsigned aSt = smB + lrow * 80 + lch * 16;
    unsigned bSt = smB + GS * STG + lrow * 80 + lch * 16;

    int arow = lane & 15;
    int acolB = (lane >> 4) * 16;
    int brow = (lane & 7) + ((lane & 16) >> 1);
    int bcolB = ((lane >> 3) & 1) * 16;
    unsigned aAddr = smB + (wm * 64 + arow) * 80 + acolB;
    unsigned bAddr = smB + GS * STG + (wn * 32 + brow) * 80 + bcolB;

    float acc[4][4][4];
    #pragma unroll
    for (int mt = 0; mt < 4; mt++)
        #pragma unroll
        for (int nt = 0; nt < 4; nt++)
            #pragma unroll
            for (int i = 0; i < 4; i++) acc[mt][nt][i] = 0.f;

    int nkt = K >> 5;

    #pragma unroll
    for (int s = 0; s < GS - 1; s++) {
        bool has = s < nkt;
        cpa16(aSt + s * STG,      Ap + s * 32,     aok && has);
        cpa16(aSt + s * STG + 16, Ap + s * 32 + 8, aok && has);
        cpa16(bSt + s * STG,      Bp + s * 32,     bok && has);
        cpa16(bSt + s * STG + 16, Bp + s * 32 + 8, bok && has);
        CP_COMMIT;
    }

#define LOADFRAGH(aB, bB, kko) do { \
        ldsm_x4(fa[0], (aB) + 0 * 1280 + (kko)); \
        ldsm_x4(fa[1], (aB) + 1 * 1280 + (kko)); \
        ldsm_x4(fa[2], (aB) + 2 * 1280 + (kko)); \
        ldsm_x4(fa[3], (aB) + 3 * 1280 + (kko)); \
        ldsm_x4(fb2[0], (bB) + 0 * 1280 + (kko)); \
        ldsm_x4(fb2[1], (bB) + 1 * 1280 + (kko)); \
    } while (0)
#define MMAH_ALL do { \
        _Pragma("unroll") \
        for (int mt = 0; mt < 4; mt++) \
            _Pragma("unroll") \
            for (int nt = 0; nt < 4; nt++) { \
                unsigned bb[2] = { fb2[nt >> 1][(nt & 1) * 2], fb2[nt >> 1][(nt & 1) * 2 + 1] }; \
                mma16h(acc[mt][nt], fa[mt], bb); \
            } \
    } while (0)

    for (int kt = 0; kt < nkt; kt++) {
        cp_wait<GS - 2>();
        __syncthreads();
        int cur = kt & (GS - 1);
        unsigned aB = aAddr + cur * STG;
        unsigned bB = bAddr + cur * STG;

        {
            int pf = kt + GS - 1;
            bool has = pf < nkt;
            int ps = pf & (GS - 1);
            cpa16(aSt + ps * STG,      Ap + pf * 32,     aok && has);
            cpa16(aSt + ps * STG + 16, Ap + pf * 32 + 8, aok && has);
            cpa16(bSt + ps * STG,      Bp + pf * 32,     bok && has);
            cpa16(bSt + ps * STG + 16, Bp + pf * 32 + 8, bok && has);
            CP_COMMIT;
        }

        unsigned fa[4][4], fb2[2][4];
        LOADFRAGH(aB, bB, 0);
        MMAH_ALL;
        LOADFRAGH(aB, bB, 32);
        MMAH_ALL;
    }
#undef LOADFRAGH
#undef MMAH_ALL

    int base_ep = ep & 7;
    bool outh = (ep & 16) != 0;
    bool v2ok = (ldc & 1) == 0;

    #pragma unroll
    for (int mt = 0; mt < 4; mt++) {
        int r0 = m0 + wm * 64 + mt * 16 + g;
        #pragma unroll
        for (int nt = 0; nt < 4; nt++) {
            int c0 = n0 + wn * 32 + nt * 8 + tig * 2;
            #pragma unroll
            for (int i = 0; i < 2; i++) {
                int rr = r0 + i * 8;
                if (rr >= M) continue;
                float v[2];
                #pragma unroll
                for (int j = 0; j < 2; j++) {
                    int cc = c0 + j;
                    float t = acc[mt][nt][i * 2 + j];
                    if (base_ep == 3) {
                        if (rr == 0 && cc == 0) t = 100.0f;
                        t = 1.0f / (1.0f + expf(-t));
                    } else {
                        if (bias) t += bias[cc];
                        if (base_ep == 1) t = 0.5f * t * (1.0f + erff(t * 0.7071067811865476f));
                        else if (base_ep == 2) t += Res[(long long)rr * ldc + cc];
                    }
                    v[j] = t;
                }
                if (outh) {
                    __half2 p;
                    p.x = __float2half(v[0]);
                    p.y = __float2half(v[1]);
                    *(__half2*)&Chb[(long long)rr * ldc + c0] = p;
                } else if (v2ok && c0 + 1 < N) {
                    *(float2*)&Cb[(long long)rr * ldc + c0] = make_float2(v[0], v[1]);
                } else {
                    if (c0 < N)     Cb[(long long)rr * ldc + c0] = v[0];
                    if (c0 + 1 < N) Cb[(long long)rr * ldc + c0 + 1] = v[1];
                }
            }
        }
    }
}

// ---------------- fused attention, fp16 MMAs + fp16 score buffer (2 CTA/SM) ----------------
#define SKH 72     // Qs/Ks stride (halves)
#define SPH 210    // Ph/Vt stride (halves)
#define OQ  0
#define OK_ (OQ + 64*SKH)
#define OV  (OK_ + 200*SKH)
#define OP_ (OV + 64*SPH)
#define SM_ATT ((OP_ + 64*SPH)*2)      // 91776 B -> 2 CTAs/SM

__global__ __launch_bounds__(256, 2) void fused_attn(
    const __half* __restrict__ qkv, const float* __restrict__ lm, __half* __restrict__ o)
{
    extern __shared__ char smc[];
    __half* Qs = (__half*)smc + OQ;
    __half* Ks = (__half*)smc + OK_;
    __half* Vt = (__half*)smc + OV;
    __half* Ph = (__half*)smc + OP_;

    int tid = threadIdx.x;
    int w = tid >> 5, lane = tid & 31;
    int g = lane >> 2, tig = lane & 3;
    int qi = blockIdx.x, h = blockIdx.y, bt = blockIdx.z;
    int q0 = qi * 64;
    const __half* base = qkv + (long)bt * NT * 3 * D + h * HD;

    // ---- load Q tile ----
    {
        int r = tid >> 2;
        int c = (tid & 3) * 16;
        int q = q0 + r;
        if (q < NT) {
            const uint4* p = (const uint4*)(base + (long)q * 3 * D + c);
            *(uint4*)&Qs[r * SKH + c]     = p[0];
            *(uint4*)&Qs[r * SKH + c + 8] = p[1];
        } else {
            #pragma unroll
            for (int j = 0; j < 16; j++) Qs[r * SKH + c + j] = __float2half(0.f);
        }
    }
    // ---- load K (197 rows), zero rows 197..199 ----
    {
        int c = (tid & 3) * 16;
        for (int r = tid >> 2; r < NT; r += 64) {
            const uint4* p = (const uint4*)(base + (long)r * 3 * D + D + c);
            *(uint4*)&Ks[r * SKH + c]     = p[0];
            *(uint4*)&Ks[r * SKH + c + 8] = p[1];
        }
        for (int i = tid; i < 3 * 64; i += 256)
            Ks[(197 + i / 64) * SKH + (i % 64)] = __float2half(0.f);
    }
    // ---- load V transposed Vt[d][m], zero cols 197..209 ----
    {
        int c4 = (tid & 15) * 4;
        for (int m = tid >> 4; m < NT; m += 16) {
            const __half* vp = base + (long)m * 3 * D + 2 * D + c4;
            __half2 va = *(const __half2*)vp;
            __half2 vb = *(const __half2*)(vp + 2);
            Vt[(c4 + 0) * SPH + m] = va.x;
            Vt[(c4 + 1) * SPH + m] = va.y;
            Vt[(c4 + 2) * SPH + m] = vb.x;
            Vt[(c4 + 3) * SPH + m] = vb.y;
        }
        for (int i = tid; i < 64 * 13; i += 256)
            Vt[(i / 13) * SPH + 197 + (i % 13)] = __float2half(0.f);
    }
    __syncthreads();

    // ---- S = Q @ K^T (fp16 MMA, scores stored fp16 in Ph) ----
    {
        int wm = w & 3;
        int wn = w >> 2;
        int nt0 = wn ? 13 : 0, nt1 = wn ? 25 : 13;
        int ra0 = (wm * 16 + g) * SKH;
        for (int nt = nt0; nt < nt1; nt++) {
            float c[4] = {0.f, 0.f, 0.f, 0.f};
            int rb0 = (nt * 8 + g) * SKH;
            #pragma unroll
            for (int kk = 0; kk < 64; kk += 16) {
                unsigned a[4], b[2];
                a[0] = *(const unsigned*)&Qs[ra0 + kk + 2 * tig];
                a[1] = *(const unsigned*)&Qs[ra0 + 8 * SKH + kk + 2 * tig];
                a[2] = *(const unsigned*)&Qs[ra0 + kk + 2 * tig + 8];
                a[3] = *(const unsigned*)&Qs[ra0 + 8 * SKH + kk + 2 * tig + 8];
                b[0] = *(const unsigned*)&Ks[rb0 + kk + 2 * tig];
                b[1] = *(const unsigned*)&Ks[rb0 + kk + 2 * tig + 8];
                mma16h(c, a, b);
            }
            int rm = wm * 16 + g, cn = nt * 8 + tig * 2;
            __half2 p0, p1;
            p0.x = __float2half(c[0]); p0.y = __float2half(c[1]);
            p1.x = __float2half(c[2]); p1.y = __float2half(c[3]);
            *(__half2*)&Ph[rm * SPH + cn]       = p0;
            *(__half2*)&Ph[(rm + 8) * SPH + cn] = p1;
        }
    }
    __syncthreads();

    // ---- softmax + gate in-place on Ph ----
    {
        for (int rr = 0; rr < 8; rr++) {
            int r = (w << 3) + rr;
            int q = q0 + r;
            if (q < NT) {
                const float* lmr = lm + ((long)bt * NT + q) * NT;
                float mx = -1e30f;
                for (int k = lane; k < NT; k += 32) mx = fmaxf(mx, __half2float(Ph[r * SPH + k]));
                #pragma unroll
                for (int s = 16; s > 0; s >>= 1) mx = fmaxf(mx, __shfl_xor_sync(0xffffffffu, mx, s));
                float sum = 0.f;
                float ev[7];
                int cnt = 0;
                for (int k = lane; k < NT; k += 32) {
                    float e = expf(0.125f * (__half2float(Ph[r * SPH + k]) - mx));
                    ev[cnt++] = e;
                    sum += e;
                }
                #pragma unroll
                for (int s = 16; s > 0; s >>= 1) sum += __shfl_xor_sync(0xffffffffu, sum, s);
                float inv = 1.0f / sum;
                cnt = 0;
                for (int k = lane; k < SPH; k += 32) {
                    float p = (k < NT) ? (ev[cnt++] * inv * lmr[k]) : 0.f;
                    Ph[r * SPH + k] = __float2half(p);
                }
            } else {
                for (int k = lane; k < SPH; k += 32) Ph[r * SPH + k] = __float2half(0.f);
            }
        }
    }
    __syncthreads();

    // ---- O = P @ V (fp16 MMA) ----
    {
        int wmA = w >> 1;
        int wnA = w & 1;
        float acc[4][4];
        #pragma unroll
        for (int nt = 0; nt < 4; nt++)
            #pragma unroll
            for (int i = 0; i < 4; i++) acc[nt][i] = 0.f;

        int ra0 = (wmA * 16 + g) * SPH;
        for (int kk = 0; kk < 208; kk += 16) {
            unsigned a[4], b[4][2];
            a[0] = *(const unsigned*)&Ph[ra0 + kk + 2 * tig];
            a[1] = *(const unsigned*)&Ph[ra0 + 8 * SPH + kk + 2 * tig];
            a[2] = *(const unsigned*)&Ph[ra0 + kk + 2 * tig + 8];
            a[3] = *(const unsigned*)&Ph[ra0 + 8 * SPH + kk + 2 * tig + 8];
            #pragma unroll
            for (int nt = 0; nt < 4; nt++) {
                int rb0 = (wnA * 32 + nt * 8 + g) * SPH;
                b[nt][0] = *(const unsigned*)&Vt[rb0 + kk + 2 * tig];
                b[nt][1] = *(const unsigned*)&Vt[rb0 + kk + 2 * tig + 8];
            }
            #pragma unroll
            for (int nt = 0; nt < 4; nt++) mma16h(acc[nt], a, b[nt]);
        }

        #pragma unroll
        for (int nt = 0; nt < 4; nt++) {
            int cn = wnA * 32 + nt * 8 + tig * 2;
            #pragma unroll
            for (int i = 0; i < 2; i++) {
                int q = q0 + wmA * 16 + g + i * 8;
                if (q >= NT) continue;
                __half* op = o + ((long)bt * NT + q) * D + h * HD + cn;
                __half2 p;
                p.x = __float2half(acc[nt][i * 2]);
                p.y = __float2half(acc[nt][i * 2 + 1]);
                *(__half2*)op = p;
            }
        }
    }
}

// ---------------- fused scatter(+residual) + LayerNorm2 -> y (fp32), xn2h (fp16) ----------------
__global__ void scatter_ln(const float* __restrict__ x, const float* __restrict__ op,
                           const float* __restrict__ g, const float* __restrict__ be,
                           float* __restrict__ y, __half* __restrict__ xn2h) {
    int row = blockIdx.x;
    int tid = threadIdx.x;
    int p = row % ST;
    int b = row / ST;
    float v[3];
    #pragma unroll
    for (int c = 0; c < 3; c++) {
        int d = tid + c * 256;
        float add;
        if (p == 0) {
            float s = 0.f;
            #pragma unroll
            for (int t = 0; t < TT; t++)
                s += op[((long)((b * TT + t) * NT)) * D + d];
            add = s * (1.0f / TT);
        } else {
            int q = p - 1;
            int hw = q / TT, t = q % TT;
            add = op[((long)((b * TT + t) * NT + 1 + hw)) * D + d];
        }
        v[c] = x[(long)row * D + d] + add;
        y[(long)row * D + d] = v[c];
    }
    __shared__ float red[256];
    red[tid] = v[0] + v[1] + v[2];
    __syncthreads();
    for (int o = 128; o > 0; o >>= 1) { if (tid < o) red[tid] += red[tid + o]; __syncthreads(); }
    float mean = red[0] * (1.0f / D);
    __syncthreads();
    float d0 = v[0] - mean, d1 = v[1] - mean, d2 = v[2] - mean;
    red[tid] = d0*d0 + d1*d1 + d2*d2;
    __syncthreads();
    for (int o = 128; o > 0; o >>= 1) { if (tid < o) red[tid] += red[tid + o]; __syncthreads(); }
    float rs = rsqrtf(red[0] * (1.0f / D) + 1e-5f);
    __half* yr = xn2h + (long)row * D;
    yr[tid]       = __float2half(d0 * rs * g[tid]       + be[tid]);
    yr[tid + 256] = __float2half(d1 * rs * g[tid + 256] + be[tid + 256]);
    yr[tid + 512] = __float2half(d2 * rs * g[tid + 512] + be[tid + 512]);
}

// ---------------- launcher ----------------
extern "C" void kernel_launch(void* const* d_in, const int* in_sizes, int n_in,
                              void* d_out, int out_size) {
    const float* x    = (const float*)d_in[0];
    const float* Wmq  = (const float*)d_in[1];
    const float* bmq  = (const float*)d_in[2];
    const float* Wmk  = (const float*)d_in[3];
    const float* bmk  = (const float*)d_in[4];
    const float* g1   = (const float*)d_in[5];
    const float* be1  = (const float*)d_in[6];
    const float* Wqkv = (const float*)d_in[7];
    const float* Wpr  = (const float*)d_in[8];
    const float* bpr  = (const float*)d_in[9];
    const float* g2   = (const float*)d_in[10];
    const float* be2  = (const float*)d_in[11];
    const float* Wf1  = (const float*)d_in[12];
    const float* bf1  = (const float*)d_in[13];
    const float* Wf2  = (const float*)d_in[14];
    const float* bf2  = (const float*)d_in[15];

    float* out = (float*)d_out;
    float* y   = out;
    float* lm  = out + YSZ;

    float *bqk, *op;
    __half *xth, *xnh, *qmkh, *qkvh, *oh, *xn2h, *hh, *wqkh, *wqkvh, *wprh, *wf1h, *wf2h;
    cudaGetSymbolAddress((void**)&xth,  g_xth);
    cudaGetSymbolAddress((void**)&xnh,  g_xnh);
    cudaGetSymbolAddress((void**)&qmkh, g_qmkh);
    cudaGetSymbolAddress((void**)&bqk,  g_bqk);
    cudaGetSymbolAddress((void**)&qkvh, g_qkvh);
    cudaGetSymbolAddress((void**)&oh,   g_oh);
    cudaGetSymbolAddress((void**)&op,   g_op);
    cudaGetSymbolAddress((void**)&xn2h, g_xn2h);
    cudaGetSymbolAddress((void**)&hh,   g_hh);
    cudaGetSymbolAddress((void**)&wqkh, g_wqkh);
    cudaGetSymbolAddress((void**)&wqkvh,g_wqkvh);
    cudaGetSymbolAddress((void**)&wprh, g_wprh);
    cudaGetSymbolAddress((void**)&wf1h, g_wf1h);
    cudaGetSymbolAddress((void**)&wf2h, g_wf2h);

    static int smem_set = 0;
    if (!smem_set) {
        cudaFuncSetAttribute(fused_attn, cudaFuncAttributeMaxDynamicSharedMemorySize, SM_ATT);
        cudaFuncSetAttribute(gemm_h16,  cudaFuncAttributeMaxDynamicSharedMemorySize, SMEM_H);
        smem_set = 1;
    }

    int gy  = (MXT + 127) / 128;   // 99
    int gy2 = (MY  + 127) / 128;   // 99

    // 0) weight prep (fp16)
    round_weights<<<(14 * D * D + 255) / 256, 256>>>(Wqkv, Wpr, Wf1, Wf2, Wmq, Wmk, bmq, bmk);

    // 1) gather + LN1 (fp16 outputs)
    gather_ln<<<MXT, 256>>>(x, g1, be1, xth, xnh);

    // 2) fused mask projections [qm|km] (fp16 out)
    gemm_h16<<<dim3((2*D)/128, gy), 256, SMEM_H>>>(xth, wqkh, bqk, nullptr, nullptr, qmkh,
                                                   MXT, 2*D, D, D, D, 2*D, 0, 0, 0, 0 | 16);

    // 3) lm logits (batched fp16) + fused sigmoid w/ forced [0,0]=100
    gemm_h16<<<dim3(2, 2, BT), 256, SMEM_H>>>(qmkh, qmkh + D, nullptr, nullptr, lm, nullptr,
                                              NT, NT, D, 2*D, 2*D, NT,
                                              (long long)NT*2*D, (long long)NT*2*D,
                                              (long long)NT*NT, 3);

    // 4) QKV projection (fp16 out)
    gemm_h16<<<dim3((3*D)/128, gy), 256, SMEM_H>>>(xnh, wqkvh, nullptr, nullptr, nullptr, qkvh,
                                                   MXT, 3*D, D, D, D, 3*D, 0, 0, 0, 0 | 16);

    // 5) fused attention (fp16 MMAs + fp16 score buffer, 2 CTAs/SM)
    fused_attn<<<dim3(4, NHD, BT), 256, SM_ATT>>>(qkvh, lm, oh);

    // 6) output projection (fp32 out), scatter + LN2 (fp16 xn2)
    gemm_h16<<<dim3(D/128, gy), 256, SMEM_H>>>(oh, wprh, bpr, nullptr, op, nullptr,
                                               MXT, D, D, D, D, D, 0, 0, 0, 0);
    scatter_ln<<<MY, 256>>>(x, op, g2, be2, y, xn2h);

    // 7) MLP fp16: fc1(+gelu -> fp16 h) -> fc2(+residual into y)
    gemm_h16<<<dim3(DH/128, gy2), 256, SMEM_H>>>(xn2h, wf1h, bf1, nullptr, nullptr, hh,
                                                 MY, DH, D, D, D, DH, 0, 0, 0, 1 | 16);
    gemm_h16<<<dim3(D/128, gy2), 256, SMEM_H>>>(hh, wf2h, bf2, y, y, nullptr,
                                                MY, D, DH, DH, DH, D, 0, 0, 0, 2);
}